// round 1
// baseline (speedup 1.0000x reference)
#include <cuda_runtime.h>
#include <math.h>

#define BB 2
#define TT 2048
#define CC 1024
#define HH 16
#define HD 64
#define C3 3072

// Scratch (allocation-free rule: __device__ globals)
__device__ float g_qkv[(size_t)BB * TT * C3];   // 4096 x 3072
__device__ float g_attn[(size_t)BB * TT * CC];  // 4096 x 1024

// ---------------------------------------------------------------------------
// SGEMM (NT): C[m][n] = sum_k A[m*K+k] * W[n*K+k]
// 128x128 tile, BK=16, 256 threads, 8x8 per-thread micro-tile.
// ---------------------------------------------------------------------------
__global__ __launch_bounds__(256) void sgemm_nt(
    const float* __restrict__ A, const float* __restrict__ W,
    float* __restrict__ Cout, int M, int N, int K)
{
    __shared__ float As[16][128];
    __shared__ float Bs[16][128];

    const int tid = threadIdx.x;
    const int tx = tid & 15;        // 0..15 -> N direction
    const int ty = tid >> 4;        // 0..15 -> M direction
    const int a_row = tid >> 2;     // 0..63
    const int a_c4  = (tid & 3) << 2;  // 0,4,8,12

    const float* Ap = A + (size_t)blockIdx.y * 128 * K;
    const float* Wp = W + (size_t)blockIdx.x * 128 * K;

    float acc[8][8];
#pragma unroll
    for (int i = 0; i < 8; i++)
#pragma unroll
        for (int j = 0; j < 8; j++) acc[i][j] = 0.f;

    for (int k0 = 0; k0 < K; k0 += 16) {
        float4 va0 = *(const float4*)(Ap + (size_t)a_row * K + k0 + a_c4);
        float4 va1 = *(const float4*)(Ap + (size_t)(a_row + 64) * K + k0 + a_c4);
        float4 vb0 = *(const float4*)(Wp + (size_t)a_row * K + k0 + a_c4);
        float4 vb1 = *(const float4*)(Wp + (size_t)(a_row + 64) * K + k0 + a_c4);

        As[a_c4 + 0][a_row] = va0.x; As[a_c4 + 1][a_row] = va0.y;
        As[a_c4 + 2][a_row] = va0.z; As[a_c4 + 3][a_row] = va0.w;
        As[a_c4 + 0][a_row + 64] = va1.x; As[a_c4 + 1][a_row + 64] = va1.y;
        As[a_c4 + 2][a_row + 64] = va1.z; As[a_c4 + 3][a_row + 64] = va1.w;
        Bs[a_c4 + 0][a_row] = vb0.x; Bs[a_c4 + 1][a_row] = vb0.y;
        Bs[a_c4 + 2][a_row] = vb0.z; Bs[a_c4 + 3][a_row] = vb0.w;
        Bs[a_c4 + 0][a_row + 64] = vb1.x; Bs[a_c4 + 1][a_row + 64] = vb1.y;
        Bs[a_c4 + 2][a_row + 64] = vb1.z; Bs[a_c4 + 3][a_row + 64] = vb1.w;

        __syncthreads();

#pragma unroll
        for (int kk = 0; kk < 16; kk++) {
            float af[8], bf[8];
            *(float4*)&af[0] = *(const float4*)&As[kk][ty * 8];
            *(float4*)&af[4] = *(const float4*)&As[kk][ty * 8 + 4];
            *(float4*)&bf[0] = *(const float4*)&Bs[kk][tx * 8];
            *(float4*)&bf[4] = *(const float4*)&Bs[kk][tx * 8 + 4];
#pragma unroll
            for (int i = 0; i < 8; i++)
#pragma unroll
                for (int j = 0; j < 8; j++)
                    acc[i][j] += af[i] * bf[j];
        }
        __syncthreads();
    }

    float* Cp = Cout + (size_t)(blockIdx.y * 128 + ty * 8) * N + blockIdx.x * 128 + tx * 8;
#pragma unroll
    for (int i = 0; i < 8; i++) {
        *(float4*)(Cp + (size_t)i * N)     = make_float4(acc[i][0], acc[i][1], acc[i][2], acc[i][3]);
        *(float4*)(Cp + (size_t)i * N + 4) = make_float4(acc[i][4], acc[i][5], acc[i][6], acc[i][7]);
    }
}

// ---------------------------------------------------------------------------
// RoPE: in-place on q and k slices of g_qkv. One thread per (token, head, pair).
// ---------------------------------------------------------------------------
__global__ void rope_kernel()
{
    int i = blockIdx.x * blockDim.x + threadIdx.x;
    const int total = BB * TT * HH * (HD / 2);   // 2,097,152
    if (i >= total) return;

    int n = i >> 9;        // token index (B*T), 512 pairs per token
    int r = i & 511;
    int h = r >> 5;        // head
    int j = r & 31;        // pair index within head

    int t = n & (TT - 1);

    // inv_freq = 10000^(-j/32) = exp(-j * ln(10000)/32)
    float inv_freq = (float)exp(-(double)j * 0.28782313662425575);
    float f = (float)t * inv_freq;
    float c = cosf(f);
    float s = sinf(f);

    float* p = g_qkv + (size_t)n * C3 + h * HD + 2 * j;
    float qr = p[0], qi = p[1];
    p[0] = qr * c - qi * s;
    p[1] = qr * s + qi * c;

    float* pk = p + CC;
    float kr = pk[0], ki = pk[1];
    pk[0] = kr * c - ki * s;
    pk[1] = kr * s + ki * c;
}

// ---------------------------------------------------------------------------
// Causal flash attention, fp32. Grid: (T/128 q-tiles, B*H).
// 128 threads; thread owns one q row (q + acc in registers).
// K/V tiles of 64 keys staged in smem; smem reads are uniform -> broadcast.
// ---------------------------------------------------------------------------
__global__ __launch_bounds__(128) void attn_kernel()
{
    const int bh = blockIdx.y;
    const int b = bh >> 4;
    const int h = bh & 15;
    const int qt = blockIdx.x;
    const int tid = threadIdx.x;
    const int t = qt * 128 + tid;          // global q position
    const float scale = 0.125f;            // 1/sqrt(64)

    const float* base = g_qkv + (size_t)b * TT * C3;

    __shared__ float Ks[64][64];
    __shared__ float Vs[64][64];

    float q[64];
    {
        const float4* qp = (const float4*)(base + (size_t)t * C3 + h * HD);
#pragma unroll
        for (int i = 0; i < 16; i++) {
            float4 v = qp[i];
            q[4 * i] = v.x; q[4 * i + 1] = v.y; q[4 * i + 2] = v.z; q[4 * i + 3] = v.w;
        }
    }

    float acc[64];
#pragma unroll
    for (int d = 0; d < 64; d++) acc[d] = 0.f;
    float m = -1e30f, l = 0.f;

    const int nkt = qt * 2 + 2;            // key tiles of 64 covering causal span
    for (int kt = 0; kt < nkt; kt++) {
        const int k0 = kt * 64;
        __syncthreads();
        {
            const int c4 = (tid & 15) << 2;
            const int r0 = tid >> 4;
#pragma unroll
            for (int it = 0; it < 8; it++) {
                int rr = r0 + it * 8;
                const float* src = base + (size_t)(k0 + rr) * C3 + CC + h * HD + c4;
                *(float4*)&Ks[rr][c4] = *(const float4*)src;
                *(float4*)&Vs[rr][c4] = *(const float4*)(src + CC);
            }
        }
        __syncthreads();

#pragma unroll 1
        for (int ch = 0; ch < 4; ch++) {
            float s[16];
#pragma unroll
            for (int jj = 0; jj < 16; jj++) {
                const int j = ch * 16 + jj;
                float sum = 0.f;
#pragma unroll
                for (int d = 0; d < 64; d++) sum += q[d] * Ks[j][d];
                s[jj] = (k0 + j <= t) ? sum * scale : -1e30f;
            }
            float mc = m;
#pragma unroll
            for (int jj = 0; jj < 16; jj++) mc = fmaxf(mc, s[jj]);
            float corr = __expf(m - mc);
            m = mc;
            l *= corr;
#pragma unroll
            for (int d = 0; d < 64; d++) acc[d] *= corr;
#pragma unroll
            for (int jj = 0; jj < 16; jj++) {
                float p = __expf(s[jj] - mc);
                l += p;
                const int j = ch * 16 + jj;
#pragma unroll
                for (int d = 0; d < 64; d++) acc[d] += p * Vs[j][d];
            }
        }
    }

    const float inv = 1.f / l;
    float* op = g_attn + (size_t)(b * TT + t) * CC + h * HD;
#pragma unroll
    for (int i = 0; i < 16; i++) {
        *(float4*)(op + 4 * i) = make_float4(acc[4 * i] * inv, acc[4 * i + 1] * inv,
                                             acc[4 * i + 2] * inv, acc[4 * i + 3] * inv);
    }
}

// ---------------------------------------------------------------------------
extern "C" void kernel_launch(void* const* d_in, const int* in_sizes, int n_in,
                              void* d_out, int out_size)
{
    const float* x     = (const float*)d_in[0];   // (B,T,C) = (4096,1024)
    const float* w_qkv = (const float*)d_in[1];   // (3072,1024)
    const float* w_out = (const float*)d_in[2];   // (1024,1024)
    float* out = (float*)d_out;                   // (4096,1024)

    float* qkv;  cudaGetSymbolAddress((void**)&qkv,  g_qkv);
    float* attn; cudaGetSymbolAddress((void**)&attn, g_attn);

    const int M = BB * TT;  // 4096

    // 1) qkv = x @ w_qkv^T
    sgemm_nt<<<dim3(C3 / 128, M / 128), 256>>>(x, w_qkv, qkv, M, C3, CC);

    // 2) RoPE in-place on q,k slices
    const int rope_total = BB * TT * HH * (HD / 2);
    rope_kernel<<<(rope_total + 255) / 256, 256>>>();

    // 3) causal flash attention -> g_attn (B,T,H*D)
    attn_kernel<<<dim3(TT / 128, BB * HH), 128>>>();

    // 4) out = attn @ w_out^T
    sgemm_nt<<<dim3(CC / 128, M / 128), 256>>>(attn, w_out, out, M, CC, CC);
}

// round 2
// speedup vs baseline: 1.2264x; 1.2264x over previous
#include <cuda_runtime.h>
#include <math.h>

#define BB 2
#define TT 2048
#define CC 1024
#define HH 16
#define HD 64
#define C3 3072

// Scratch (allocation-free rule: __device__ globals)
__device__ float g_qkv[(size_t)BB * TT * C3];   // 4096 x 3072
__device__ float g_attn[(size_t)BB * TT * CC];  // 4096 x 1024

// ---------------------------------------------------------------------------
// SGEMM (NT): C[m][n] = sum_k A[m*K+k] * W[n*K+k]
// 128x128 tile, BK=16, 256 threads, 8x8 per-thread micro-tile.
// ---------------------------------------------------------------------------
__global__ __launch_bounds__(256) void sgemm_nt(
    const float* __restrict__ A, const float* __restrict__ W,
    float* __restrict__ Cout, int M, int N, int K)
{
    __shared__ float As[16][128];
    __shared__ float Bs[16][128];

    const int tid = threadIdx.x;
    const int tx = tid & 15;        // 0..15 -> N direction
    const int ty = tid >> 4;        // 0..15 -> M direction
    const int a_row = tid >> 2;     // 0..63
    const int a_c4  = (tid & 3) << 2;  // 0,4,8,12

    const float* Ap = A + (size_t)blockIdx.y * 128 * K;
    const float* Wp = W + (size_t)blockIdx.x * 128 * K;

    float acc[8][8];
#pragma unroll
    for (int i = 0; i < 8; i++)
#pragma unroll
        for (int j = 0; j < 8; j++) acc[i][j] = 0.f;

    for (int k0 = 0; k0 < K; k0 += 16) {
        float4 va0 = *(const float4*)(Ap + (size_t)a_row * K + k0 + a_c4);
        float4 va1 = *(const float4*)(Ap + (size_t)(a_row + 64) * K + k0 + a_c4);
        float4 vb0 = *(const float4*)(Wp + (size_t)a_row * K + k0 + a_c4);
        float4 vb1 = *(const float4*)(Wp + (size_t)(a_row + 64) * K + k0 + a_c4);

        As[a_c4 + 0][a_row] = va0.x; As[a_c4 + 1][a_row] = va0.y;
        As[a_c4 + 2][a_row] = va0.z; As[a_c4 + 3][a_row] = va0.w;
        As[a_c4 + 0][a_row + 64] = va1.x; As[a_c4 + 1][a_row + 64] = va1.y;
        As[a_c4 + 2][a_row + 64] = va1.z; As[a_c4 + 3][a_row + 64] = va1.w;
        Bs[a_c4 + 0][a_row] = vb0.x; Bs[a_c4 + 1][a_row] = vb0.y;
        Bs[a_c4 + 2][a_row] = vb0.z; Bs[a_c4 + 3][a_row] = vb0.w;
        Bs[a_c4 + 0][a_row + 64] = vb1.x; Bs[a_c4 + 1][a_row + 64] = vb1.y;
        Bs[a_c4 + 2][a_row + 64] = vb1.z; Bs[a_c4 + 3][a_row + 64] = vb1.w;

        __syncthreads();

#pragma unroll
        for (int kk = 0; kk < 16; kk++) {
            float af[8], bf[8];
            *(float4*)&af[0] = *(const float4*)&As[kk][ty * 8];
            *(float4*)&af[4] = *(const float4*)&As[kk][ty * 8 + 4];
            *(float4*)&bf[0] = *(const float4*)&Bs[kk][tx * 8];
            *(float4*)&bf[4] = *(const float4*)&Bs[kk][tx * 8 + 4];
#pragma unroll
            for (int i = 0; i < 8; i++)
#pragma unroll
                for (int j = 0; j < 8; j++)
                    acc[i][j] += af[i] * bf[j];
        }
        __syncthreads();
    }

    float* Cp = Cout + (size_t)(blockIdx.y * 128 + ty * 8) * N + blockIdx.x * 128 + tx * 8;
#pragma unroll
    for (int i = 0; i < 8; i++) {
        *(float4*)(Cp + (size_t)i * N)     = make_float4(acc[i][0], acc[i][1], acc[i][2], acc[i][3]);
        *(float4*)(Cp + (size_t)i * N + 4) = make_float4(acc[i][4], acc[i][5], acc[i][6], acc[i][7]);
    }
}

// ---------------------------------------------------------------------------
// RoPE: in-place on q and k slices of g_qkv. One thread per (token, head, pair).
// ---------------------------------------------------------------------------
__global__ void rope_kernel()
{
    int i = blockIdx.x * blockDim.x + threadIdx.x;
    const int total = BB * TT * HH * (HD / 2);   // 2,097,152
    if (i >= total) return;

    int n = i >> 9;        // token index (B*T), 512 pairs per token
    int r = i & 511;
    int h = r >> 5;        // head
    int j = r & 31;        // pair index within head

    int t = n & (TT - 1);

    // inv_freq = 10000^(-j/32) = exp(-j * ln(10000)/32)
    float inv_freq = (float)exp(-(double)j * 0.28782313662425575);
    float f = (float)t * inv_freq;
    float c = cosf(f);
    float s = sinf(f);

    float* p = g_qkv + (size_t)n * C3 + h * HD + 2 * j;
    float qr = p[0], qi = p[1];
    p[0] = qr * c - qi * s;
    p[1] = qr * s + qi * c;

    float* pk = p + CC;
    float kr = pk[0], ki = pk[1];
    pk[0] = kr * c - ki * s;
    pk[1] = kr * s + ki * c;
}

// ---------------------------------------------------------------------------
// Causal flash attention, fp32, 2-D register-tiled.
// CTA: 64 q-rows x full head. 128 threads, thread tile 8 rows x 4 cols.
// Q,K staged d-major (transposed, pad 66) for outer-product fragments.
// P staged [key][row] (pad 66). V natural [key][d].
// Grid: (32 q-tiles reversed, 32 b*h).
// ---------------------------------------------------------------------------
#define QS_OFF 0
#define KS_OFF 4224
#define PS_OFF 8448
#define VS_OFF 12672
#define MS_OFF 16768
#define LS_OFF 16832
#define CS_OFF 16896
#define ATTN_SMEM_FLOATS 16960
#define ATTN_SMEM_BYTES (ATTN_SMEM_FLOATS * 4)

__global__ __launch_bounds__(128) void attn_kernel()
{
    extern __shared__ float sm[];
    float* smQ = sm + QS_OFF;   // [64 d][66] (d-major, col = q-row)
    float* smK = sm + KS_OFF;   // [64 d][66] (d-major, col = key)
    float* smP = sm + PS_OFF;   // [64 key][66] (col = q-row)
    float* smV = sm + VS_OFF;   // [64 key][64 d] natural
    float* smM = sm + MS_OFF;   // [64] row max
    float* smL = sm + LS_OFF;   // [64] row sum
    float* smC = sm + CS_OFF;   // [64] row corr

    const int bh = blockIdx.y;
    const int b = bh >> 4;
    const int h = bh & 15;
    const int qt = 31 - blockIdx.x;       // heavy tiles first
    const int q0 = qt * 64;
    const int tid = threadIdx.x;
    const int tx = tid & 15;              // 4 cols each
    const int ty = tid >> 4;              // 8 rows each
    const float scale = 0.125f;           // 1/sqrt(64)

    const float* base = g_qkv + (size_t)b * TT * C3;

    // Load Q tile, transposed into smQ[d][r]
    {
        const int r = tid >> 4;            // 0..7
        const int d4 = (tid & 15) * 4;
#pragma unroll
        for (int it = 0; it < 8; it++) {
            int rr = r + it * 8;
            float4 v = *(const float4*)(base + (size_t)(q0 + rr) * C3 + h * HD + d4);
            smQ[(d4 + 0) * 66 + rr] = v.x;
            smQ[(d4 + 1) * 66 + rr] = v.y;
            smQ[(d4 + 2) * 66 + rr] = v.z;
            smQ[(d4 + 3) * 66 + rr] = v.w;
        }
    }
    if (tid < 64) { smM[tid] = -1e30f; smL[tid] = 0.f; }

    float o[8][4];
#pragma unroll
    for (int i = 0; i < 8; i++)
#pragma unroll
        for (int j = 0; j < 4; j++) o[i][j] = 0.f;

    const int nkt = qt + 1;
    for (int kt = 0; kt < nkt; kt++) {
        const int k0 = kt * 64;
        __syncthreads();   // prior PV reads of smP/smV done; Q load done (kt=0)

        // Load K (transposed) and V (natural)
        {
            const int r = tid >> 4;
            const int d4 = (tid & 15) * 4;
#pragma unroll
            for (int it = 0; it < 8; it++) {
                int rr = r + it * 8;
                const float* src = base + (size_t)(k0 + rr) * C3 + CC + h * HD + d4;
                float4 kv = *(const float4*)src;
                float4 vv = *(const float4*)(src + CC);
                smK[(d4 + 0) * 66 + rr] = kv.x;
                smK[(d4 + 1) * 66 + rr] = kv.y;
                smK[(d4 + 2) * 66 + rr] = kv.z;
                smK[(d4 + 3) * 66 + rr] = kv.w;
                *(float4*)&smV[rr * 64 + d4] = vv;
            }
        }
        __syncthreads();

        // S = Q K^T : 8x4 micro-tile per thread
        float s[8][4];
#pragma unroll
        for (int i = 0; i < 8; i++)
#pragma unroll
            for (int j = 0; j < 4; j++) s[i][j] = 0.f;

#pragma unroll 4
        for (int d = 0; d < 64; d++) {
            float a[8], bf[4];
            const float* qrow = &smQ[d * 66 + ty * 8];
            const float* krow = &smK[d * 66 + tx * 4];
            *(float2*)&a[0] = *(const float2*)&qrow[0];
            *(float2*)&a[2] = *(const float2*)&qrow[2];
            *(float2*)&a[4] = *(const float2*)&qrow[4];
            *(float2*)&a[6] = *(const float2*)&qrow[6];
            *(float2*)&bf[0] = *(const float2*)&krow[0];
            *(float2*)&bf[2] = *(const float2*)&krow[2];
#pragma unroll
            for (int i = 0; i < 8; i++)
#pragma unroll
                for (int j = 0; j < 4; j++)
                    s[i][j] += a[i] * bf[j];
        }

        // Scale + causal mask (diagonal tile only), store to smP[col][row]
        const bool diag = (kt == qt);
#pragma unroll
        for (int jj = 0; jj < 4; jj++) {
            const int c = tx * 4 + jj;
            float* pp = &smP[c * 66 + ty * 8];
#pragma unroll
            for (int i2 = 0; i2 < 4; i2++) {
                int r0 = ty * 8 + i2 * 2;
                float v0 = s[i2 * 2][jj] * scale;
                float v1 = s[i2 * 2 + 1][jj] * scale;
                if (diag) {
                    if (c > r0)     v0 = -1e30f;
                    if (c > r0 + 1) v1 = -1e30f;
                }
                *(float2*)&pp[i2 * 2] = make_float2(v0, v1);
            }
        }
        __syncthreads();

        // Row-wise online softmax (threads 0..63, one row each)
        if (tid < 64) {
            const int r = tid;
            float mold = smM[r];
            float mx = mold;
#pragma unroll 8
            for (int j = 0; j < 64; j++)
                mx = fmaxf(mx, smP[j * 66 + r]);
            float lsum = 0.f;
#pragma unroll 8
            for (int j = 0; j < 64; j++) {
                float p = __expf(smP[j * 66 + r] - mx);
                smP[j * 66 + r] = p;
                lsum += p;
            }
            float corr = __expf(mold - mx);
            smM[r] = mx;
            smL[r] = smL[r] * corr + lsum;
            smC[r] = corr;
        }
        __syncthreads();

        // Rescale O and accumulate P V
#pragma unroll
        for (int i = 0; i < 8; i++) {
            float cf = smC[ty * 8 + i];
#pragma unroll
            for (int j = 0; j < 4; j++) o[i][j] *= cf;
        }
#pragma unroll 4
        for (int j = 0; j < 64; j++) {
            float a[8], bf[4];
            const float* prow = &smP[j * 66 + ty * 8];
            *(float2*)&a[0] = *(const float2*)&prow[0];
            *(float2*)&a[2] = *(const float2*)&prow[2];
            *(float2*)&a[4] = *(const float2*)&prow[4];
            *(float2*)&a[6] = *(const float2*)&prow[6];
            *(float4*)&bf[0] = *(const float4*)&smV[j * 64 + tx * 4];
#pragma unroll
            for (int i = 0; i < 8; i++)
#pragma unroll
                for (int jj = 0; jj < 4; jj++)
                    o[i][jj] += a[i] * bf[jj];
        }
    }

    // Epilogue: normalize and write
#pragma unroll
    for (int i = 0; i < 8; i++) {
        const int r = ty * 8 + i;
        float linv = 1.f / smL[r];
        float4 w = make_float4(o[i][0] * linv, o[i][1] * linv,
                               o[i][2] * linv, o[i][3] * linv);
        *(float4*)(g_attn + (size_t)(b * TT + q0 + r) * CC + h * HD + tx * 4) = w;
    }
}

// ---------------------------------------------------------------------------
extern "C" void kernel_launch(void* const* d_in, const int* in_sizes, int n_in,
                              void* d_out, int out_size)
{
    const float* x     = (const float*)d_in[0];   // (B,T,C) = (4096,1024)
    const float* w_qkv = (const float*)d_in[1];   // (3072,1024)
    const float* w_out = (const float*)d_in[2];   // (1024,1024)
    float* out = (float*)d_out;                   // (4096,1024)

    float* qkv;  cudaGetSymbolAddress((void**)&qkv,  g_qkv);
    float* attn; cudaGetSymbolAddress((void**)&attn, g_attn);

    const int M = BB * TT;  // 4096

    static int attn_smem_set = 0;
    if (!attn_smem_set) {
        cudaFuncSetAttribute(attn_kernel,
                             cudaFuncAttributeMaxDynamicSharedMemorySize,
                             ATTN_SMEM_BYTES);
        attn_smem_set = 1;
    }

    // 1) qkv = x @ w_qkv^T
    sgemm_nt<<<dim3(C3 / 128, M / 128), 256>>>(x, w_qkv, qkv, M, C3, CC);

    // 2) RoPE in-place on q,k slices
    const int rope_total = BB * TT * HH * (HD / 2);
    rope_kernel<<<(rope_total + 255) / 256, 256>>>();

    // 3) causal flash attention -> g_attn (B,T,H*D)
    attn_kernel<<<dim3(TT / 64, BB * HH), 128, ATTN_SMEM_BYTES>>>();

    // 4) out = attn @ w_out^T
    sgemm_nt<<<dim3(CC / 128, M / 128), 256>>>(attn, w_out, out, M, CC, CC);
}

// round 3
// speedup vs baseline: 1.2421x; 1.0129x over previous
#include <cuda_runtime.h>
#include <math.h>
#include <stdint.h>

#define BB 2
#define TT 2048
#define CC 1024
#define HH 16
#define HD 64
#define C3 3072

// Scratch (allocation-free rule: __device__ globals)
__device__ float g_qkv[(size_t)BB * TT * C3];   // 4096 x 3072
__device__ float g_attn[(size_t)BB * TT * CC];  // 4096 x 1024

// ---------------------------------------------------------------------------
// Packed f32x2 helpers (Blackwell FFMA2 — only reachable via PTX)
// ---------------------------------------------------------------------------
typedef unsigned long long u64t;

__device__ __forceinline__ u64t ffma2(u64t a, u64t b, u64t c) {
    u64t d;
    asm("fma.rn.f32x2 %0, %1, %2, %3;" : "=l"(d) : "l"(a), "l"(b), "l"(c));
    return d;
}
__device__ __forceinline__ u64t fmul2(u64t a, u64t b) {
    u64t d;
    asm("mul.rn.f32x2 %0, %1, %2;" : "=l"(d) : "l"(a), "l"(b));
    return d;
}
__device__ __forceinline__ u64t splat2(float x) {
    u64t d; unsigned u = __float_as_uint(x);
    asm("mov.b64 %0, {%1, %1};" : "=l"(d) : "r"(u));
    return d;
}
__device__ __forceinline__ void unpack2(u64t v, float& lo, float& hi) {
    unsigned a, b;
    asm("mov.b64 {%0, %1}, %2;" : "=r"(a), "=r"(b) : "l"(v));
    lo = __uint_as_float(a); hi = __uint_as_float(b);
}

// ---------------------------------------------------------------------------
// SGEMM (NT): C[m][n] = sum_k A[m*K+k] * W[n*K+k]
// 128x128 tile, BK=16, 256 threads, 8x8 micro-tile, FFMA2 packed along M.
// ---------------------------------------------------------------------------
__global__ __launch_bounds__(256) void sgemm_nt(
    const float* __restrict__ A, const float* __restrict__ W,
    float* __restrict__ Cout, int M, int N, int K)
{
    __shared__ float As[16][128];
    __shared__ float Bs[16][128];

    const int tid = threadIdx.x;
    const int tx = tid & 15;        // 0..15 -> N direction
    const int ty = tid >> 4;        // 0..15 -> M direction
    const int a_row = tid >> 2;     // 0..63
    const int a_c4  = (tid & 3) << 2;  // 0,4,8,12

    const float* Ap = A + (size_t)blockIdx.y * 128 * K;
    const float* Wp = W + (size_t)blockIdx.x * 128 * K;

    u64t acc[4][8];                 // [row-pair][col]
#pragma unroll
    for (int i = 0; i < 4; i++)
#pragma unroll
        for (int j = 0; j < 8; j++) acc[i][j] = 0ull;

    for (int k0 = 0; k0 < K; k0 += 16) {
        float4 va0 = *(const float4*)(Ap + (size_t)a_row * K + k0 + a_c4);
        float4 va1 = *(const float4*)(Ap + (size_t)(a_row + 64) * K + k0 + a_c4);
        float4 vb0 = *(const float4*)(Wp + (size_t)a_row * K + k0 + a_c4);
        float4 vb1 = *(const float4*)(Wp + (size_t)(a_row + 64) * K + k0 + a_c4);

        As[a_c4 + 0][a_row] = va0.x; As[a_c4 + 1][a_row] = va0.y;
        As[a_c4 + 2][a_row] = va0.z; As[a_c4 + 3][a_row] = va0.w;
        As[a_c4 + 0][a_row + 64] = va1.x; As[a_c4 + 1][a_row + 64] = va1.y;
        As[a_c4 + 2][a_row + 64] = va1.z; As[a_c4 + 3][a_row + 64] = va1.w;
        Bs[a_c4 + 0][a_row] = vb0.x; Bs[a_c4 + 1][a_row] = vb0.y;
        Bs[a_c4 + 2][a_row] = vb0.z; Bs[a_c4 + 3][a_row] = vb0.w;
        Bs[a_c4 + 0][a_row + 64] = vb1.x; Bs[a_c4 + 1][a_row + 64] = vb1.y;
        Bs[a_c4 + 2][a_row + 64] = vb1.z; Bs[a_c4 + 3][a_row + 64] = vb1.w;

        __syncthreads();

#pragma unroll
        for (int kk = 0; kk < 16; kk++) {
            // A fragment: 8 rows = 4 natural f32x2 pairs
            ulonglong2 ta0 = *(const ulonglong2*)&As[kk][ty * 8];
            ulonglong2 ta1 = *(const ulonglong2*)&As[kk][ty * 8 + 4];
            u64t a2[4] = { ta0.x, ta0.y, ta1.x, ta1.y };
            // B fragment: 8 scalars -> 8 splats
            float4 b0 = *(const float4*)&Bs[kk][tx * 8];
            float4 b1 = *(const float4*)&Bs[kk][tx * 8 + 4];
            u64t bs[8] = { splat2(b0.x), splat2(b0.y), splat2(b0.z), splat2(b0.w),
                           splat2(b1.x), splat2(b1.y), splat2(b1.z), splat2(b1.w) };
#pragma unroll
            for (int i = 0; i < 4; i++)
#pragma unroll
                for (int j = 0; j < 8; j++)
                    acc[i][j] = ffma2(a2[i], bs[j], acc[i][j]);
        }
        __syncthreads();
    }

    // Epilogue: unpack row-pairs and store
#pragma unroll
    for (int i = 0; i < 4; i++) {
        float lo[8], hi[8];
#pragma unroll
        for (int j = 0; j < 8; j++) unpack2(acc[i][j], lo[j], hi[j]);
        const int r0 = blockIdx.y * 128 + ty * 8 + 2 * i;
        float* Cp0 = Cout + (size_t)r0 * N + blockIdx.x * 128 + tx * 8;
        float* Cp1 = Cp0 + N;
        *(float4*)(Cp0)     = make_float4(lo[0], lo[1], lo[2], lo[3]);
        *(float4*)(Cp0 + 4) = make_float4(lo[4], lo[5], lo[6], lo[7]);
        *(float4*)(Cp1)     = make_float4(hi[0], hi[1], hi[2], hi[3]);
        *(float4*)(Cp1 + 4) = make_float4(hi[4], hi[5], hi[6], hi[7]);
    }
}

// ---------------------------------------------------------------------------
// RoPE: in-place on q and k slices of g_qkv. One thread per (token, head, pair).
// ---------------------------------------------------------------------------
__global__ void rope_kernel()
{
    int i = blockIdx.x * blockDim.x + threadIdx.x;
    const int total = BB * TT * HH * (HD / 2);   // 2,097,152
    if (i >= total) return;

    int n = i >> 9;        // token index (B*T), 512 pairs per token
    int r = i & 511;
    int h = r >> 5;        // head
    int j = r & 31;        // pair index within head

    int t = n & (TT - 1);

    float inv_freq = (float)exp(-(double)j * 0.28782313662425575);
    float f = (float)t * inv_freq;
    float c = cosf(f);
    float s = sinf(f);

    float* p = g_qkv + (size_t)n * C3 + h * HD + 2 * j;
    float qr = p[0], qi = p[1];
    p[0] = qr * c - qi * s;
    p[1] = qr * s + qi * c;

    float* pk = p + CC;
    float kr = pk[0], ki = pk[1];
    pk[0] = kr * c - ki * s;
    pk[1] = kr * s + ki * c;
}

// ---------------------------------------------------------------------------
// Causal flash attention, fp32, 2-D register-tiled with FFMA2.
// CTA: 64 q-rows x full head. 128 threads, thread tile 8 rows x 4 cols,
// accumulators packed along rows (4 f32x2-pairs x 4 cols).
// Q,K staged d-major (pitch 68). P staged [key][row] (pitch 68). V natural.
// ---------------------------------------------------------------------------
#define PITCH 68
#define QS_OFF 0
#define KS_OFF 4352
#define PS_OFF 8704
#define VS_OFF 13056
#define MS_OFF 17152
#define LS_OFF 17216
#define CS_OFF 17280
#define ATTN_SMEM_FLOATS 17344
#define ATTN_SMEM_BYTES (ATTN_SMEM_FLOATS * 4)

__global__ __launch_bounds__(128) void attn_kernel()
{
    extern __shared__ float sm[];
    float* smQ = sm + QS_OFF;   // [64 d][68] (d-major, col = q-row)
    float* smK = sm + KS_OFF;   // [64 d][68] (d-major, col = key)
    float* smP = sm + PS_OFF;   // [64 key][68] (col = q-row)
    float* smV = sm + VS_OFF;   // [64 key][64 d] natural
    float* smM = sm + MS_OFF;   // [64] row max
    float* smL = sm + LS_OFF;   // [64] row sum
    float* smC = sm + CS_OFF;   // [64] row corr

    const int bh = blockIdx.y;
    const int b = bh >> 4;
    const int h = bh & 15;
    const int qt = 31 - blockIdx.x;       // heavy tiles first
    const int q0 = qt * 64;
    const int tid = threadIdx.x;
    const int tx = tid & 15;              // 4 cols each
    const int ty = tid >> 4;              // 8 rows each
    const float scale = 0.125f;           // 1/sqrt(64)

    const float* base = g_qkv + (size_t)b * TT * C3;

    // Load Q tile, transposed into smQ[d][r]
    {
        const int r = tid >> 4;            // 0..7
        const int d4 = (tid & 15) * 4;
#pragma unroll
        for (int it = 0; it < 8; it++) {
            int rr = r + it * 8;
            float4 v = *(const float4*)(base + (size_t)(q0 + rr) * C3 + h * HD + d4);
            smQ[(d4 + 0) * PITCH + rr] = v.x;
            smQ[(d4 + 1) * PITCH + rr] = v.y;
            smQ[(d4 + 2) * PITCH + rr] = v.z;
            smQ[(d4 + 3) * PITCH + rr] = v.w;
        }
    }
    if (tid < 64) { smM[tid] = -1e30f; smL[tid] = 0.f; }

    u64t o2[4][4];                         // [row-pair][col]
#pragma unroll
    for (int i = 0; i < 4; i++)
#pragma unroll
        for (int j = 0; j < 4; j++) o2[i][j] = 0ull;

    const int nkt = qt + 1;
    for (int kt = 0; kt < nkt; kt++) {
        const int k0 = kt * 64;
        __syncthreads();   // prior PV reads of smP/smV done; Q load done (kt=0)

        // Load K (transposed) and V (natural)
        {
            const int r = tid >> 4;
            const int d4 = (tid & 15) * 4;
#pragma unroll
            for (int it = 0; it < 8; it++) {
                int rr = r + it * 8;
                const float* src = base + (size_t)(k0 + rr) * C3 + CC + h * HD + d4;
                float4 kv = *(const float4*)src;
                float4 vv = *(const float4*)(src + CC);
                smK[(d4 + 0) * PITCH + rr] = kv.x;
                smK[(d4 + 1) * PITCH + rr] = kv.y;
                smK[(d4 + 2) * PITCH + rr] = kv.z;
                smK[(d4 + 3) * PITCH + rr] = kv.w;
                *(float4*)&smV[rr * 64 + d4] = vv;
            }
        }
        __syncthreads();

        // S = Q K^T : 8x4 micro-tile per thread, rows packed in f32x2
        u64t s2[4][4];
#pragma unroll
        for (int i = 0; i < 4; i++)
#pragma unroll
            for (int j = 0; j < 4; j++) s2[i][j] = 0ull;

#pragma unroll 4
        for (int d = 0; d < 64; d++) {
            ulonglong2 tq0 = *(const ulonglong2*)&smQ[d * PITCH + ty * 8];
            ulonglong2 tq1 = *(const ulonglong2*)&smQ[d * PITCH + ty * 8 + 4];
            u64t a2[4] = { tq0.x, tq0.y, tq1.x, tq1.y };
            float2 kk0 = *(const float2*)&smK[d * PITCH + tx * 4];
            float2 kk1 = *(const float2*)&smK[d * PITCH + tx * 4 + 2];
            u64t bs[4] = { splat2(kk0.x), splat2(kk0.y), splat2(kk1.x), splat2(kk1.y) };
#pragma unroll
            for (int i = 0; i < 4; i++)
#pragma unroll
                for (int j = 0; j < 4; j++)
                    s2[i][j] = ffma2(a2[i], bs[j], s2[i][j]);
        }

        // Scale + causal mask (diagonal tile only), store to smP[col][row]
        const bool diag = (kt == qt);
#pragma unroll
        for (int jj = 0; jj < 4; jj++) {
            const int c = tx * 4 + jj;
            float* pp = &smP[c * PITCH + ty * 8];
#pragma unroll
            for (int i2 = 0; i2 < 4; i2++) {
                int r0 = ty * 8 + i2 * 2;
                float v0, v1;
                unpack2(s2[i2][jj], v0, v1);
                v0 *= scale; v1 *= scale;
                if (diag) {
                    if (c > r0)     v0 = -1e30f;
                    if (c > r0 + 1) v1 = -1e30f;
                }
                *(float2*)&pp[i2 * 2] = make_float2(v0, v1);
            }
        }
        __syncthreads();

        // Row-wise online softmax (threads 0..63, one row each)
        if (tid < 64) {
            const int r = tid;
            float mold = smM[r];
            float mx = mold;
#pragma unroll 8
            for (int j = 0; j < 64; j++)
                mx = fmaxf(mx, smP[j * PITCH + r]);
            float lsum = 0.f;
#pragma unroll 8
            for (int j = 0; j < 64; j++) {
                float p = __expf(smP[j * PITCH + r] - mx);
                smP[j * PITCH + r] = p;
                lsum += p;
            }
            float corr = __expf(mold - mx);
            smM[r] = mx;
            smL[r] = smL[r] * corr + lsum;
            smC[r] = corr;
        }
        __syncthreads();

        // Rescale O (packed) and accumulate P V
#pragma unroll
        for (int i = 0; i < 4; i++) {
            u64t cf2 = *(const u64t*)&smC[ty * 8 + 2 * i];
#pragma unroll
            for (int j = 0; j < 4; j++) o2[i][j] = fmul2(o2[i][j], cf2);
        }
#pragma unroll 4
        for (int j = 0; j < 64; j++) {
            ulonglong2 tp0 = *(const ulonglong2*)&smP[j * PITCH + ty * 8];
            ulonglong2 tp1 = *(const ulonglong2*)&smP[j * PITCH + ty * 8 + 4];
            u64t a2[4] = { tp0.x, tp0.y, tp1.x, tp1.y };
            float4 vv = *(const float4*)&smV[j * 64 + tx * 4];
            u64t bs[4] = { splat2(vv.x), splat2(vv.y), splat2(vv.z), splat2(vv.w) };
#pragma unroll
            for (int i = 0; i < 4; i++)
#pragma unroll
                for (int jj = 0; jj < 4; jj++)
                    o2[i][jj] = ffma2(a2[i], bs[jj], o2[i][jj]);
        }
    }

    // Epilogue: normalize and write (unpack row pairs)
#pragma unroll
    for (int i = 0; i < 4; i++) {
        const int r0 = ty * 8 + 2 * i;
        float l0 = 1.f / smL[r0];
        float l1 = 1.f / smL[r0 + 1];
        float lo[4], hi[4];
#pragma unroll
        for (int j = 0; j < 4; j++) unpack2(o2[i][j], lo[j], hi[j]);
        float* op0 = g_attn + (size_t)(b * TT + q0 + r0) * CC + h * HD + tx * 4;
        *(float4*)op0        = make_float4(lo[0] * l0, lo[1] * l0, lo[2] * l0, lo[3] * l0);
        *(float4*)(op0 + CC) = make_float4(hi[0] * l1, hi[1] * l1, hi[2] * l1, hi[3] * l1);
    }
}

// ---------------------------------------------------------------------------
extern "C" void kernel_launch(void* const* d_in, const int* in_sizes, int n_in,
                              void* d_out, int out_size)
{
    const float* x     = (const float*)d_in[0];   // (B,T,C) = (4096,1024)
    const float* w_qkv = (const float*)d_in[1];   // (3072,1024)
    const float* w_out = (const float*)d_in[2];   // (1024,1024)
    float* out = (float*)d_out;                   // (4096,1024)

    float* qkv;  cudaGetSymbolAddress((void**)&qkv,  g_qkv);
    float* attn; cudaGetSymbolAddress((void**)&attn, g_attn);

    const int M = BB * TT;  // 4096

    static int attn_smem_set = 0;
    if (!attn_smem_set) {
        cudaFuncSetAttribute(attn_kernel,
                             cudaFuncAttributeMaxDynamicSharedMemorySize,
                             ATTN_SMEM_BYTES);
        attn_smem_set = 1;
    }

    // 1) qkv = x @ w_qkv^T
    sgemm_nt<<<dim3(C3 / 128, M / 128), 256>>>(x, w_qkv, qkv, M, C3, CC);

    // 2) RoPE in-place on q,k slices
    const int rope_total = BB * TT * HH * (HD / 2);
    rope_kernel<<<(rope_total + 255) / 256, 256>>>();

    // 3) causal flash attention -> g_attn (B,T,H*D)
    attn_kernel<<<dim3(TT / 64, BB * HH), 128, ATTN_SMEM_BYTES>>>();

    // 4) out = attn @ w_out^T
    sgemm_nt<<<dim3(CC / 128, M / 128), 256>>>(attn, w_out, out, M, CC, CC);
}

// round 4
// speedup vs baseline: 1.7620x; 1.4186x over previous
#include <cuda_runtime.h>
#include <cuda_bf16.h>
#include <math.h>
#include <stdint.h>

#define BB 2
#define TT 2048
#define CC 1024
#define HH 16
#define HD 64
#define C3 3072

// Scratch (allocation-free rule: __device__ globals)
__device__ float g_qkv[(size_t)BB * TT * C3];   // 4096 x 3072
__device__ float g_attn[(size_t)BB * TT * CC];  // 4096 x 1024

// ---------------------------------------------------------------------------
// Packed f32x2 helpers (used by attention)
// ---------------------------------------------------------------------------
typedef unsigned long long u64t;

__device__ __forceinline__ u64t ffma2(u64t a, u64t b, u64t c) {
    u64t d;
    asm("fma.rn.f32x2 %0, %1, %2, %3;" : "=l"(d) : "l"(a), "l"(b), "l"(c));
    return d;
}
__device__ __forceinline__ u64t fmul2(u64t a, u64t b) {
    u64t d;
    asm("mul.rn.f32x2 %0, %1, %2;" : "=l"(d) : "l"(a), "l"(b));
    return d;
}
__device__ __forceinline__ u64t splat2(float x) {
    u64t d; unsigned u = __float_as_uint(x);
    asm("mov.b64 %0, {%1, %1};" : "=l"(d) : "r"(u));
    return d;
}
__device__ __forceinline__ void unpack2(u64t v, float& lo, float& hi) {
    unsigned a, b;
    asm("mov.b64 {%0, %1}, %2;" : "=r"(a), "=r"(b) : "l"(v));
    lo = __uint_as_float(a); hi = __uint_as_float(b);
}

// ---------------------------------------------------------------------------
// Tensor-core GEMM (NT): C[m][n] = sum_k A[m*K+k] * W[n*K+k]
// bf16 3-term split (hi*hi + hi*lo + lo*hi) with fp32 accumulators.
// CTA 128x128, BK=16, 8 warps (2x4), warp tile 64x32, double-buffered smem.
// ---------------------------------------------------------------------------
#define GP 24          // smem row pitch in halves (16 data + 8 pad, 48B rows)
#define STAGE_H 12288  // halves per stage (4 tiles x 128 x GP)
#define GEMM_SMEM_BYTES (2 * STAGE_H * 2)

__device__ __forceinline__ void mma_bf16(float* c, const unsigned* a, const unsigned* b) {
    asm("mma.sync.aligned.m16n8k16.row.col.f32.bf16.bf16.f32 "
        "{%0,%1,%2,%3},{%4,%5,%6,%7},{%8,%9},{%0,%1,%2,%3};"
        : "+f"(c[0]), "+f"(c[1]), "+f"(c[2]), "+f"(c[3])
        : "r"(a[0]), "r"(a[1]), "r"(a[2]), "r"(a[3]), "r"(b[0]), "r"(b[1]));
}

__device__ __forceinline__ void ldm_x4(unsigned* r, uint32_t addr) {
    asm volatile("ldmatrix.sync.aligned.m8n8.x4.shared.b16 {%0,%1,%2,%3}, [%4];"
                 : "=r"(r[0]), "=r"(r[1]), "=r"(r[2]), "=r"(r[3]) : "r"(addr));
}
__device__ __forceinline__ void ldm_x2(unsigned* r, uint32_t addr) {
    asm volatile("ldmatrix.sync.aligned.m8n8.x2.shared.b16 {%0,%1}, [%2];"
                 : "=r"(r[0]), "=r"(r[1]) : "r"(addr));
}

// split one float into bf16 hi + bf16 lo (round-to-nearest)
__device__ __forceinline__ void split_bf16(float f, unsigned short& h, unsigned short& l) {
    __nv_bfloat16 bh = __float2bfloat16_rn(f);
    float fh = __bfloat162float(bh);
    __nv_bfloat16 bl = __float2bfloat16_rn(f - fh);
    h = *reinterpret_cast<unsigned short*>(&bh);
    l = *reinterpret_cast<unsigned short*>(&bl);
}

// convert float4 -> packed hi (2xu32) and lo (2xu32), store 8B each
__device__ __forceinline__ void cvt_store(unsigned short* hi_t, unsigned short* lo_t,
                                          int row, int col, float4 v) {
    unsigned short h0, h1, h2, h3, l0, l1, l2, l3;
    split_bf16(v.x, h0, l0); split_bf16(v.y, h1, l1);
    split_bf16(v.z, h2, l2); split_bf16(v.w, h3, l3);
    uint2 hp = make_uint2((unsigned)h0 | ((unsigned)h1 << 16),
                          (unsigned)h2 | ((unsigned)h3 << 16));
    uint2 lp = make_uint2((unsigned)l0 | ((unsigned)l1 << 16),
                          (unsigned)l2 | ((unsigned)l3 << 16));
    *(uint2*)&hi_t[row * GP + col] = hp;
    *(uint2*)&lo_t[row * GP + col] = lp;
}

__global__ __launch_bounds__(256, 1) void gemm_bf16x3(
    const float* __restrict__ A, const float* __restrict__ W,
    float* __restrict__ Cout, int M, int N, int K)
{
    extern __shared__ unsigned short sh[];

    const int tid = threadIdx.x;
    const int wid = tid >> 5;
    const int lane = tid & 31;
    const int warp_m = wid >> 2;       // 0..1
    const int warp_n = wid & 3;        // 0..3

    const float* Ap = A + (size_t)blockIdx.y * 128 * K;
    const float* Wp = W + (size_t)blockIdx.x * 128 * K;

    // loader slots: 512 float4 per tile, thread covers slots tid and tid+256
    const int r0 = tid >> 2,        c0 = (tid & 3) * 4;
    const int r1 = (tid + 256) >> 2, c1 = ((tid + 256) & 3) * 4;

    const uint32_t smem_u32 = (uint32_t)__cvta_generic_to_shared(sh);

    // ldmatrix lane addressing (halves)
    const int a_lrow = (lane & 7) + ((lane >> 3) & 1) * 8;
    const int a_lcol = ((lane >> 4) & 1) * 8;
    const int b_lrow = lane & 7;
    const int b_lcol = ((lane >> 3) & 1) * 8;

    float acc[4][4][4];
#pragma unroll
    for (int i = 0; i < 4; i++)
#pragma unroll
        for (int j = 0; j < 4; j++)
#pragma unroll
            for (int q = 0; q < 4; q++) acc[i][j][q] = 0.f;

    const int nstage = K / 16;

    // prefetch stage 0
    float4 va0 = *(const float4*)(Ap + (size_t)r0 * K + c0);
    float4 va1 = *(const float4*)(Ap + (size_t)r1 * K + c1);
    float4 vb0 = *(const float4*)(Wp + (size_t)r0 * K + c0);
    float4 vb1 = *(const float4*)(Wp + (size_t)r1 * K + c1);
    {
        unsigned short* Ahi = sh;                 unsigned short* Alo = sh + 3072;
        unsigned short* Bhi = sh + 6144;          unsigned short* Blo = sh + 9216;
        cvt_store(Ahi, Alo, r0, c0, va0);
        cvt_store(Ahi, Alo, r1, c1, va1);
        cvt_store(Bhi, Blo, r0, c0, vb0);
        cvt_store(Bhi, Blo, r1, c1, vb1);
    }
    __syncthreads();

    for (int s = 0; s < nstage; s++) {
        if (s + 1 < nstage) {
            const int k0 = (s + 1) * 16;
            va0 = *(const float4*)(Ap + (size_t)r0 * K + k0 + c0);
            va1 = *(const float4*)(Ap + (size_t)r1 * K + k0 + c1);
            vb0 = *(const float4*)(Wp + (size_t)r0 * K + k0 + c0);
            vb1 = *(const float4*)(Wp + (size_t)r1 * K + k0 + c1);
        }

        // compute on buffer s&1
        {
            const uint32_t base = smem_u32 + (unsigned)(s & 1) * (STAGE_H * 2);
            const uint32_t baseAhi = base;
            const uint32_t baseAlo = base + 3072 * 2;
            const uint32_t baseBhi = base + 6144 * 2;
            const uint32_t baseBlo = base + 9216 * 2;

            unsigned Ah[4][4], Al[4][4], Bh[4][2], Bl[4][2];
#pragma unroll
            for (int am = 0; am < 4; am++) {
                const uint32_t off =
                    (uint32_t)(((warp_m * 64 + am * 16 + a_lrow) * GP + a_lcol) * 2);
                ldm_x4(Ah[am], baseAhi + off);
                ldm_x4(Al[am], baseAlo + off);
            }
#pragma unroll
            for (int an = 0; an < 4; an++) {
                const uint32_t off =
                    (uint32_t)(((warp_n * 32 + an * 8 + b_lrow) * GP + b_lcol) * 2);
                ldm_x2(Bh[an], baseBhi + off);
                ldm_x2(Bl[an], baseBlo + off);
            }
#pragma unroll
            for (int am = 0; am < 4; am++)
#pragma unroll
                for (int an = 0; an < 4; an++)
                    mma_bf16(acc[am][an], Ah[am], Bh[an]);
#pragma unroll
            for (int am = 0; am < 4; am++)
#pragma unroll
                for (int an = 0; an < 4; an++)
                    mma_bf16(acc[am][an], Ah[am], Bl[an]);
#pragma unroll
            for (int am = 0; am < 4; am++)
#pragma unroll
                for (int an = 0; an < 4; an++)
                    mma_bf16(acc[am][an], Al[am], Bh[an]);
        }

        if (s + 1 < nstage) {
            unsigned short* st = sh + (unsigned)((s + 1) & 1) * STAGE_H;
            cvt_store(st,        st + 3072, r0, c0, va0);
            cvt_store(st,        st + 3072, r1, c1, va1);
            cvt_store(st + 6144, st + 9216, r0, c0, vb0);
            cvt_store(st + 6144, st + 9216, r1, c1, vb1);
            __syncthreads();
        }
    }

    // Epilogue
    const int mbase = blockIdx.y * 128 + warp_m * 64 + (lane >> 2);
    const int nbase = blockIdx.x * 128 + warp_n * 32 + (lane & 3) * 2;
#pragma unroll
    for (int am = 0; am < 4; am++) {
#pragma unroll
        for (int an = 0; an < 4; an++) {
            const int r = mbase + am * 16;
            const int c = nbase + an * 8;
            *(float2*)&Cout[(size_t)r * N + c]       = make_float2(acc[am][an][0], acc[am][an][1]);
            *(float2*)&Cout[(size_t)(r + 8) * N + c] = make_float2(acc[am][an][2], acc[am][an][3]);
        }
    }
}

// ---------------------------------------------------------------------------
// RoPE: in-place on q and k slices of g_qkv. One thread per (token, head, pair).
// ---------------------------------------------------------------------------
__global__ void rope_kernel()
{
    int i = blockIdx.x * blockDim.x + threadIdx.x;
    const int total = BB * TT * HH * (HD / 2);   // 2,097,152
    if (i >= total) return;

    int n = i >> 9;        // token index (B*T), 512 pairs per token
    int r = i & 511;
    int h = r >> 5;        // head
    int j = r & 31;        // pair index within head

    int t = n & (TT - 1);

    float inv_freq = (float)exp(-(double)j * 0.28782313662425575);
    float f = (float)t * inv_freq;
    float c = cosf(f);
    float s = sinf(f);

    float* p = g_qkv + (size_t)n * C3 + h * HD + 2 * j;
    float qr = p[0], qi = p[1];
    p[0] = qr * c - qi * s;
    p[1] = qr * s + qi * c;

    float* pk = p + CC;
    float kr = pk[0], ki = pk[1];
    pk[0] = kr * c - ki * s;
    pk[1] = kr * s + ki * c;
}

// ---------------------------------------------------------------------------
// Causal flash attention, fp32, 2-D register-tiled with FFMA2.
// CTA: 64 q-rows x full head. 128 threads, thread tile 8 rows x 4 cols.
// ---------------------------------------------------------------------------
#define PITCH 68
#define QS_OFF 0
#define KS_OFF 4352
#define PS_OFF 8704
#define VS_OFF 13056
#define MS_OFF 17152
#define LS_OFF 17216
#define CS_OFF 17280
#define ATTN_SMEM_FLOATS 17344
#define ATTN_SMEM_BYTES (ATTN_SMEM_FLOATS * 4)

__global__ __launch_bounds__(128) void attn_kernel()
{
    extern __shared__ float sm[];
    float* smQ = sm + QS_OFF;   // [64 d][68] (d-major, col = q-row)
    float* smK = sm + KS_OFF;   // [64 d][68] (d-major, col = key)
    float* smP = sm + PS_OFF;   // [64 key][68] (col = q-row)
    float* smV = sm + VS_OFF;   // [64 key][64 d] natural
    float* smM = sm + MS_OFF;   // [64] row max
    float* smL = sm + LS_OFF;   // [64] row sum
    float* smC = sm + CS_OFF;   // [64] row corr

    const int bh = blockIdx.y;
    const int b = bh >> 4;
    const int h = bh & 15;
    const int qt = 31 - blockIdx.x;       // heavy tiles first
    const int q0 = qt * 64;
    const int tid = threadIdx.x;
    const int tx = tid & 15;              // 4 cols each
    const int ty = tid >> 4;              // 8 rows each
    const float scale = 0.125f;           // 1/sqrt(64)

    const float* base = g_qkv + (size_t)b * TT * C3;

    // Load Q tile, transposed into smQ[d][r]
    {
        const int r = tid >> 4;            // 0..7
        const int d4 = (tid & 15) * 4;
#pragma unroll
        for (int it = 0; it < 8; it++) {
            int rr = r + it * 8;
            float4 v = *(const float4*)(base + (size_t)(q0 + rr) * C3 + h * HD + d4);
            smQ[(d4 + 0) * PITCH + rr] = v.x;
            smQ[(d4 + 1) * PITCH + rr] = v.y;
            smQ[(d4 + 2) * PITCH + rr] = v.z;
            smQ[(d4 + 3) * PITCH + rr] = v.w;
        }
    }
    if (tid < 64) { smM[tid] = -1e30f; smL[tid] = 0.f; }

    u64t o2[4][4];                         // [row-pair][col]
#pragma unroll
    for (int i = 0; i < 4; i++)
#pragma unroll
        for (int j = 0; j < 4; j++) o2[i][j] = 0ull;

    const int nkt = qt + 1;
    for (int kt = 0; kt < nkt; kt++) {
        const int k0 = kt * 64;
        __syncthreads();   // prior PV reads of smP/smV done; Q load done (kt=0)

        // Load K (transposed) and V (natural)
        {
            const int r = tid >> 4;
            const int d4 = (tid & 15) * 4;
#pragma unroll
            for (int it = 0; it < 8; it++) {
                int rr = r + it * 8;
                const float* src = base + (size_t)(k0 + rr) * C3 + CC + h * HD + d4;
                float4 kv = *(const float4*)src;
                float4 vv = *(const float4*)(src + CC);
                smK[(d4 + 0) * PITCH + rr] = kv.x;
                smK[(d4 + 1) * PITCH + rr] = kv.y;
                smK[(d4 + 2) * PITCH + rr] = kv.z;
                smK[(d4 + 3) * PITCH + rr] = kv.w;
                *(float4*)&smV[rr * 64 + d4] = vv;
            }
        }
        __syncthreads();

        // S = Q K^T : 8x4 micro-tile per thread, rows packed in f32x2
        u64t s2[4][4];
#pragma unroll
        for (int i = 0; i < 4; i++)
#pragma unroll
            for (int j = 0; j < 4; j++) s2[i][j] = 0ull;

#pragma unroll 4
        for (int d = 0; d < 64; d++) {
            ulonglong2 tq0 = *(const ulonglong2*)&smQ[d * PITCH + ty * 8];
            ulonglong2 tq1 = *(const ulonglong2*)&smQ[d * PITCH + ty * 8 + 4];
            u64t a2[4] = { tq0.x, tq0.y, tq1.x, tq1.y };
            float2 kk0 = *(const float2*)&smK[d * PITCH + tx * 4];
            float2 kk1 = *(const float2*)&smK[d * PITCH + tx * 4 + 2];
            u64t bs[4] = { splat2(kk0.x), splat2(kk0.y), splat2(kk1.x), splat2(kk1.y) };
#pragma unroll
            for (int i = 0; i < 4; i++)
#pragma unroll
                for (int j = 0; j < 4; j++)
                    s2[i][j] = ffma2(a2[i], bs[j], s2[i][j]);
        }

        // Scale + causal mask (diagonal tile only), store to smP[col][row]
        const bool diag = (kt == qt);
#pragma unroll
        for (int jj = 0; jj < 4; jj++) {
            const int c = tx * 4 + jj;
            float* pp = &smP[c * PITCH + ty * 8];
#pragma unroll
            for (int i2 = 0; i2 < 4; i2++) {
                int r0 = ty * 8 + i2 * 2;
                float v0, v1;
                unpack2(s2[i2][jj], v0, v1);
                v0 *= scale; v1 *= scale;
                if (diag) {
                    if (c > r0)     v0 = -1e30f;
                    if (c > r0 + 1) v1 = -1e30f;
                }
                *(float2*)&pp[i2 * 2] = make_float2(v0, v1);
            }
        }
        __syncthreads();

        // Row-wise online softmax (threads 0..63, one row each)
        if (tid < 64) {
            const int r = tid;
            float mold = smM[r];
            float mx = mold;
#pragma unroll 8
            for (int j = 0; j < 64; j++)
                mx = fmaxf(mx, smP[j * PITCH + r]);
            float lsum = 0.f;
#pragma unroll 8
            for (int j = 0; j < 64; j++) {
                float p = __expf(smP[j * PITCH + r] - mx);
                smP[j * PITCH + r] = p;
                lsum += p;
            }
            float corr = __expf(mold - mx);
            smM[r] = mx;
            smL[r] = smL[r] * corr + lsum;
            smC[r] = corr;
        }
        __syncthreads();

        // Rescale O (packed) and accumulate P V
#pragma unroll
        for (int i = 0; i < 4; i++) {
            u64t cf2 = *(const u64t*)&smC[ty * 8 + 2 * i];
#pragma unroll
            for (int j = 0; j < 4; j++) o2[i][j] = fmul2(o2[i][j], cf2);
        }
#pragma unroll 4
        for (int j = 0; j < 64; j++) {
            ulonglong2 tp0 = *(const ulonglong2*)&smP[j * PITCH + ty * 8];
            ulonglong2 tp1 = *(const ulonglong2*)&smP[j * PITCH + ty * 8 + 4];
            u64t a2[4] = { tp0.x, tp0.y, tp1.x, tp1.y };
            float4 vv = *(const float4*)&smV[j * 64 + tx * 4];
            u64t bs[4] = { splat2(vv.x), splat2(vv.y), splat2(vv.z), splat2(vv.w) };
#pragma unroll
            for (int i = 0; i < 4; i++)
#pragma unroll
                for (int jj = 0; jj < 4; jj++)
                    o2[i][jj] = ffma2(a2[i], bs[jj], o2[i][jj]);
        }
    }

    // Epilogue: normalize and write (unpack row pairs)
#pragma unroll
    for (int i = 0; i < 4; i++) {
        const int r0 = ty * 8 + 2 * i;
        float l0 = 1.f / smL[r0];
        float l1 = 1.f / smL[r0 + 1];
        float lo[4], hi[4];
#pragma unroll
        for (int j = 0; j < 4; j++) unpack2(o2[i][j], lo[j], hi[j]);
        float* op0 = g_attn + (size_t)(b * TT + q0 + r0) * CC + h * HD + tx * 4;
        *(float4*)op0        = make_float4(lo[0] * l0, lo[1] * l0, lo[2] * l0, lo[3] * l0);
        *(float4*)(op0 + CC) = make_float4(hi[0] * l1, hi[1] * l1, hi[2] * l1, hi[3] * l1);
    }
}

// ---------------------------------------------------------------------------
extern "C" void kernel_launch(void* const* d_in, const int* in_sizes, int n_in,
                              void* d_out, int out_size)
{
    const float* x     = (const float*)d_in[0];   // (B,T,C) = (4096,1024)
    const float* w_qkv = (const float*)d_in[1];   // (3072,1024)
    const float* w_out = (const float*)d_in[2];   // (1024,1024)
    float* out = (float*)d_out;                   // (4096,1024)

    float* qkv;  cudaGetSymbolAddress((void**)&qkv,  g_qkv);
    float* attn; cudaGetSymbolAddress((void**)&attn, g_attn);

    const int M = BB * TT;  // 4096

    static int attr_set = 0;
    if (!attr_set) {
        cudaFuncSetAttribute(attn_kernel,
                             cudaFuncAttributeMaxDynamicSharedMemorySize,
                             ATTN_SMEM_BYTES);
        cudaFuncSetAttribute(gemm_bf16x3,
                             cudaFuncAttributeMaxDynamicSharedMemorySize,
                             GEMM_SMEM_BYTES);
        attr_set = 1;
    }

    // 1) qkv = x @ w_qkv^T
    gemm_bf16x3<<<dim3(C3 / 128, M / 128), 256, GEMM_SMEM_BYTES>>>(x, w_qkv, qkv, M, C3, CC);

    // 2) RoPE in-place on q,k slices
    const int rope_total = BB * TT * HH * (HD / 2);
    rope_kernel<<<(rope_total + 255) / 256, 256>>>();

    // 3) causal flash attention -> g_attn (B,T,H*D)
    attn_kernel<<<dim3(TT / 64, BB * HH), 128, ATTN_SMEM_BYTES>>>();

    // 4) out = attn @ w_out^T
    gemm_bf16x3<<<dim3(CC / 128, M / 128), 256, GEMM_SMEM_BYTES>>>(attn, w_out, out, M, CC, CC);
}

// round 5
// speedup vs baseline: 2.9015x; 1.6467x over previous
#include <cuda_runtime.h>
#include <cuda_bf16.h>
#include <math.h>
#include <stdint.h>

#define BB 2
#define TT 2048
#define CC 1024
#define HH 16
#define HD 64
#define C3 3072

// Scratch (allocation-free rule: __device__ globals)
__device__ float g_qkv[(size_t)BB * TT * C3];   // 4096 x 3072
__device__ float g_attn[(size_t)BB * TT * CC];  // 4096 x 1024

// ---------------------------------------------------------------------------
// mma / ldmatrix helpers
// ---------------------------------------------------------------------------
__device__ __forceinline__ void mma_bf16(float* c, const unsigned* a, const unsigned* b) {
    asm("mma.sync.aligned.m16n8k16.row.col.f32.bf16.bf16.f32 "
        "{%0,%1,%2,%3},{%4,%5,%6,%7},{%8,%9},{%0,%1,%2,%3};"
        : "+f"(c[0]), "+f"(c[1]), "+f"(c[2]), "+f"(c[3])
        : "r"(a[0]), "r"(a[1]), "r"(a[2]), "r"(a[3]), "r"(b[0]), "r"(b[1]));
}
__device__ __forceinline__ void ldm_x4(unsigned* r, uint32_t addr) {
    asm volatile("ldmatrix.sync.aligned.m8n8.x4.shared.b16 {%0,%1,%2,%3}, [%4];"
                 : "=r"(r[0]), "=r"(r[1]), "=r"(r[2]), "=r"(r[3]) : "r"(addr));
}
__device__ __forceinline__ void ldm_x2(unsigned* r, uint32_t addr) {
    asm volatile("ldmatrix.sync.aligned.m8n8.x2.shared.b16 {%0,%1}, [%2];"
                 : "=r"(r[0]), "=r"(r[1]) : "r"(addr));
}
__device__ __forceinline__ void ldm_x2t(unsigned* r, uint32_t addr) {
    asm volatile("ldmatrix.sync.aligned.m8n8.x2.trans.shared.b16 {%0,%1}, [%2];"
                 : "=r"(r[0]), "=r"(r[1]) : "r"(addr));
}

// pack two fp32 -> bf16x2 (lo in low half)
__device__ __forceinline__ unsigned pack2bf(float lo, float hi) {
    unsigned r;
    asm("cvt.rn.bf16x2.f32 %0, %1, %2;" : "=r"(r) : "f"(hi), "f"(lo));
    return r;
}
__device__ __forceinline__ float bflo(unsigned u) { return __uint_as_float(u << 16); }
__device__ __forceinline__ float bfhi(unsigned u) { return __uint_as_float(u & 0xffff0000u); }

// fast exp on fma/alu pipes (no MUFU): e^x for x <= 0, exact-enough (~1e-7 rel)
__device__ __forceinline__ float fexp(float x) {
    float y = x * 1.4426950408889634f;
    y = fmaxf(y, -126.0f);
    int ni = __float2int_rd(y);
    float f = y - (float)ni;
    float p = 0.0018775767f;
    p = fmaf(p, f, 0.0089893397f);
    p = fmaf(p, f, 0.0558282185f);
    p = fmaf(p, f, 0.2400789568f);
    p = fmaf(p, f, 0.6931531203f);
    p = fmaf(p, f, 0.9999999702f);
    return __uint_as_float(__float_as_uint(p) + ((unsigned)ni << 23));
}

// split float4 -> bf16 hi pair + lo pair
__device__ __forceinline__ void split4(float4 v, uint2& hp, uint2& lp) {
    unsigned h01 = pack2bf(v.x, v.y);
    unsigned h23 = pack2bf(v.z, v.w);
    float r0 = v.x - bflo(h01);
    float r1 = v.y - bfhi(h01);
    float r2 = v.z - bflo(h23);
    float r3 = v.w - bfhi(h23);
    hp = make_uint2(h01, h23);
    lp = make_uint2(pack2bf(r0, r1), pack2bf(r2, r3));
}

// ---------------------------------------------------------------------------
// Tensor-core GEMM (NT): C[m][n] = sum_k A[m*K+k] * W[n*K+k]
// bf16 3-term split, CTA 128x128, BK=16, 8 warps, double-buffered smem.
// ---------------------------------------------------------------------------
#define GP 24          // smem row pitch in halves
#define STAGE_H 12288
#define GEMM_SMEM_BYTES (2 * STAGE_H * 2)

__device__ __forceinline__ void cvt_store(unsigned short* hi_t, unsigned short* lo_t,
                                          int row, int col, float4 v) {
    uint2 hp, lp;
    split4(v, hp, lp);
    *(uint2*)&hi_t[row * GP + col] = hp;
    *(uint2*)&lo_t[row * GP + col] = lp;
}

__global__ __launch_bounds__(256, 1) void gemm_bf16x3(
    const float* __restrict__ A, const float* __restrict__ W,
    float* __restrict__ Cout, int M, int N, int K)
{
    extern __shared__ unsigned short sh[];

    const int tid = threadIdx.x;
    const int wid = tid >> 5;
    const int lane = tid & 31;
    const int warp_m = wid >> 2;
    const int warp_n = wid & 3;

    const float* Ap = A + (size_t)blockIdx.y * 128 * K;
    const float* Wp = W + (size_t)blockIdx.x * 128 * K;

    const int r0 = tid >> 2,         c0 = (tid & 3) * 4;
    const int r1 = (tid + 256) >> 2, c1 = ((tid + 256) & 3) * 4;

    const uint32_t smem_u32 = (uint32_t)__cvta_generic_to_shared(sh);

    const int a_lrow = (lane & 7) + ((lane >> 3) & 1) * 8;
    const int a_lcol = ((lane >> 4) & 1) * 8;
    const int b_lrow = lane & 7;
    const int b_lcol = ((lane >> 3) & 1) * 8;

    float acc[4][4][4];
#pragma unroll
    for (int i = 0; i < 4; i++)
#pragma unroll
        for (int j = 0; j < 4; j++)
#pragma unroll
            for (int q = 0; q < 4; q++) acc[i][j][q] = 0.f;

    const int nstage = K / 16;

    float4 va0 = *(const float4*)(Ap + (size_t)r0 * K + c0);
    float4 va1 = *(const float4*)(Ap + (size_t)r1 * K + c1);
    float4 vb0 = *(const float4*)(Wp + (size_t)r0 * K + c0);
    float4 vb1 = *(const float4*)(Wp + (size_t)r1 * K + c1);
    cvt_store(sh,        sh + 3072, r0, c0, va0);
    cvt_store(sh,        sh + 3072, r1, c1, va1);
    cvt_store(sh + 6144, sh + 9216, r0, c0, vb0);
    cvt_store(sh + 6144, sh + 9216, r1, c1, vb1);
    __syncthreads();

    for (int s = 0; s < nstage; s++) {
        if (s + 1 < nstage) {
            const int k0 = (s + 1) * 16;
            va0 = *(const float4*)(Ap + (size_t)r0 * K + k0 + c0);
            va1 = *(const float4*)(Ap + (size_t)r1 * K + k0 + c1);
            vb0 = *(const float4*)(Wp + (size_t)r0 * K + k0 + c0);
            vb1 = *(const float4*)(Wp + (size_t)r1 * K + k0 + c1);
        }
        {
            const uint32_t base = smem_u32 + (unsigned)(s & 1) * (STAGE_H * 2);
            unsigned Ah[4][4], Al[4][4], Bh[4][2], Bl[4][2];
#pragma unroll
            for (int am = 0; am < 4; am++) {
                const uint32_t off =
                    (uint32_t)(((warp_m * 64 + am * 16 + a_lrow) * GP + a_lcol) * 2);
                ldm_x4(Ah[am], base + off);
                ldm_x4(Al[am], base + 3072 * 2 + off);
            }
#pragma unroll
            for (int an = 0; an < 4; an++) {
                const uint32_t off =
                    (uint32_t)(((warp_n * 32 + an * 8 + b_lrow) * GP + b_lcol) * 2);
                ldm_x2(Bh[an], base + 6144 * 2 + off);
                ldm_x2(Bl[an], base + 9216 * 2 + off);
            }
#pragma unroll
            for (int am = 0; am < 4; am++)
#pragma unroll
                for (int an = 0; an < 4; an++)
                    mma_bf16(acc[am][an], Ah[am], Bh[an]);
#pragma unroll
            for (int am = 0; am < 4; am++)
#pragma unroll
                for (int an = 0; an < 4; an++)
                    mma_bf16(acc[am][an], Ah[am], Bl[an]);
#pragma unroll
            for (int am = 0; am < 4; am++)
#pragma unroll
                for (int an = 0; an < 4; an++)
                    mma_bf16(acc[am][an], Al[am], Bh[an]);
        }
        if (s + 1 < nstage) {
            unsigned short* st = sh + (unsigned)((s + 1) & 1) * STAGE_H;
            cvt_store(st,        st + 3072, r0, c0, va0);
            cvt_store(st,        st + 3072, r1, c1, va1);
            cvt_store(st + 6144, st + 9216, r0, c0, vb0);
            cvt_store(st + 6144, st + 9216, r1, c1, vb1);
            __syncthreads();
        }
    }

    const int mbase = blockIdx.y * 128 + warp_m * 64 + (lane >> 2);
    const int nbase = blockIdx.x * 128 + warp_n * 32 + (lane & 3) * 2;
#pragma unroll
    for (int am = 0; am < 4; am++) {
#pragma unroll
        for (int an = 0; an < 4; an++) {
            const int r = mbase + am * 16;
            const int c = nbase + an * 8;
            *(float2*)&Cout[(size_t)r * N + c]       = make_float2(acc[am][an][0], acc[am][an][1]);
            *(float2*)&Cout[(size_t)(r + 8) * N + c] = make_float2(acc[am][an][2], acc[am][an][3]);
        }
    }
}

// ---------------------------------------------------------------------------
// RoPE: in-place on q and k slices of g_qkv.
// ---------------------------------------------------------------------------
__global__ void rope_kernel()
{
    int i = blockIdx.x * blockDim.x + threadIdx.x;
    const int total = BB * TT * HH * (HD / 2);
    if (i >= total) return;

    int n = i >> 9;
    int r = i & 511;
    int h = r >> 5;
    int j = r & 31;
    int t = n & (TT - 1);

    float inv_freq = (float)exp(-(double)j * 0.28782313662425575);
    float f = (float)t * inv_freq;
    float c = cosf(f);
    float s = sinf(f);

    float* p = g_qkv + (size_t)n * C3 + h * HD + 2 * j;
    float qr = p[0], qi = p[1];
    p[0] = qr * c - qi * s;
    p[1] = qr * s + qi * c;

    float* pk = p + CC;
    float kr = pk[0], ki = pk[1];
    pk[0] = kr * c - ki * s;
    pk[1] = kr * s + ki * c;
}

// ---------------------------------------------------------------------------
// Tensor-core causal flash attention.
// CTA: 64 q-rows, 4 warps (16 rows/warp), 64-key tiles.
// S = QK^T and O += P V via m16n8k16 bf16 with 3-term hi/lo split.
// Softmax in mma C-fragments; exp via fma-pipe polynomial (no MUFU).
// ---------------------------------------------------------------------------
#define GP2 72   // smem pitch in halves for 64-wide tiles

__global__ __launch_bounds__(128) void attn_mma()
{
    __shared__ __align__(16) unsigned short sKhi[64 * GP2];
    __shared__ __align__(16) unsigned short sKlo[64 * GP2];
    __shared__ __align__(16) unsigned short sVhi[64 * GP2];
    __shared__ __align__(16) unsigned short sVlo[64 * GP2];

    const int bh = blockIdx.y;
    const int b = bh >> 4;
    const int h = bh & 15;
    const int qt = 31 - blockIdx.x;       // heavy tiles first
    const int q0 = qt * 64;
    const int tid = threadIdx.x;
    const int wid = tid >> 5;
    const int lane = tid & 31;
    const float scale = 0.125f;

    const float* base = g_qkv + (size_t)b * TT * C3;

    const uint32_t kh_u = (uint32_t)__cvta_generic_to_shared(sKhi);
    const uint32_t kl_u = (uint32_t)__cvta_generic_to_shared(sKlo);
    const uint32_t vh_u = (uint32_t)__cvta_generic_to_shared(sVhi);
    const uint32_t vl_u = (uint32_t)__cvta_generic_to_shared(sVlo);

    const int a_lrow = (lane & 7) + ((lane >> 3) & 1) * 8;
    const int a_lcol = ((lane >> 4) & 1) * 8;

    // ---- stage Q (64 x 64) into K buffers, extract A fragments ----
#pragma unroll
    for (int it = 0; it < 8; it++) {
        int idx = tid + it * 128;               // 1024 float4 slots
        int r = idx >> 4, c4 = (idx & 15) * 4;
        float4 v = *(const float4*)(base + (size_t)(q0 + r) * C3 + h * HD + c4);
        uint2 hp, lp;
        split4(v, hp, lp);
        *(uint2*)&sKhi[r * GP2 + c4] = hp;
        *(uint2*)&sKlo[r * GP2 + c4] = lp;
    }
    __syncthreads();

    unsigned Qh[4][4], Ql[4][4];
#pragma unroll
    for (int kk = 0; kk < 4; kk++) {
        uint32_t off = (uint32_t)(((wid * 16 + a_lrow) * GP2 + kk * 16 + a_lcol) * 2);
        ldm_x4(Qh[kk], kh_u + off);
        ldm_x4(Ql[kk], kl_u + off);
    }

    float o[8][4];
#pragma unroll
    for (int nb = 0; nb < 8; nb++)
#pragma unroll
        for (int e = 0; e < 4; e++) o[nb][e] = 0.f;
    float m0 = -1e30f, m1 = -1e30f, l0 = 0.f, l1 = 0.f;

    const int rg0 = q0 + wid * 16 + (lane >> 2);
    const int rg1 = rg0 + 8;
    const int cbase = (lane & 3) * 2;

    for (int kt = 0; kt <= qt; kt++) {
        const int k0 = kt * 64;
        __syncthreads();   // previous tile's mma reads done (and Q frag extraction)

        // ---- load K,V tile, split bf16 hi/lo ----
#pragma unroll
        for (int it = 0; it < 8; it++) {
            int idx = tid + it * 128;
            int r = idx >> 4, c4 = (idx & 15) * 4;
            const float* src = base + (size_t)(k0 + r) * C3 + CC + h * HD + c4;
            float4 kv = *(const float4*)src;
            float4 vv = *(const float4*)(src + CC);
            uint2 hp, lp;
            split4(kv, hp, lp);
            *(uint2*)&sKhi[r * GP2 + c4] = hp;
            *(uint2*)&sKlo[r * GP2 + c4] = lp;
            split4(vv, hp, lp);
            *(uint2*)&sVhi[r * GP2 + c4] = hp;
            *(uint2*)&sVlo[r * GP2 + c4] = lp;
        }
        __syncthreads();

        // ---- S = Q K^T (3-pass split) ----
        float s[8][4];
#pragma unroll
        for (int nb = 0; nb < 8; nb++)
#pragma unroll
            for (int e = 0; e < 4; e++) s[nb][e] = 0.f;

#pragma unroll
        for (int kk = 0; kk < 4; kk++) {
#pragma unroll
            for (int nb = 0; nb < 8; nb++) {
                unsigned Bh[2], Bl[2];
                uint32_t off = (uint32_t)(((nb * 8 + (lane & 7)) * GP2 +
                                           kk * 16 + ((lane >> 3) & 1) * 8) * 2);
                ldm_x2(Bh, kh_u + off);
                ldm_x2(Bl, kl_u + off);
                mma_bf16(s[nb], Qh[kk], Bh);
                mma_bf16(s[nb], Qh[kk], Bl);
                mma_bf16(s[nb], Ql[kk], Bh);
            }
        }

        // ---- scale + causal mask ----
        const bool diag = (kt == qt);
#pragma unroll
        for (int nb = 0; nb < 8; nb++) {
            int c0g = k0 + nb * 8 + cbase;
#pragma unroll
            for (int e = 0; e < 4; e++) {
                int col = c0g + (e & 1);
                int row = (e < 2) ? rg0 : rg1;
                float v = s[nb][e] * scale;
                if (diag && col > row) v = -1e30f;
                s[nb][e] = v;
            }
        }

        // ---- online softmax (registers + quad shfl) ----
        float mx0 = -1e30f, mx1 = -1e30f;
#pragma unroll
        for (int nb = 0; nb < 8; nb++) {
            mx0 = fmaxf(mx0, fmaxf(s[nb][0], s[nb][1]));
            mx1 = fmaxf(mx1, fmaxf(s[nb][2], s[nb][3]));
        }
        mx0 = fmaxf(mx0, __shfl_xor_sync(0xffffffffu, mx0, 1));
        mx0 = fmaxf(mx0, __shfl_xor_sync(0xffffffffu, mx0, 2));
        mx1 = fmaxf(mx1, __shfl_xor_sync(0xffffffffu, mx1, 1));
        mx1 = fmaxf(mx1, __shfl_xor_sync(0xffffffffu, mx1, 2));

        float nm0 = fmaxf(m0, mx0), nm1 = fmaxf(m1, mx1);
        float corr0 = fexp(m0 - nm0), corr1 = fexp(m1 - nm1);
        m0 = nm0; m1 = nm1;

        float ls0 = 0.f, ls1 = 0.f;
#pragma unroll
        for (int nb = 0; nb < 8; nb++) {
            s[nb][0] = fexp(s[nb][0] - nm0); ls0 += s[nb][0];
            s[nb][1] = fexp(s[nb][1] - nm0); ls0 += s[nb][1];
            s[nb][2] = fexp(s[nb][2] - nm1); ls1 += s[nb][2];
            s[nb][3] = fexp(s[nb][3] - nm1); ls1 += s[nb][3];
        }
        ls0 += __shfl_xor_sync(0xffffffffu, ls0, 1);
        ls0 += __shfl_xor_sync(0xffffffffu, ls0, 2);
        ls1 += __shfl_xor_sync(0xffffffffu, ls1, 1);
        ls1 += __shfl_xor_sync(0xffffffffu, ls1, 2);
        l0 = l0 * corr0 + ls0;
        l1 = l1 * corr1 + ls1;

#pragma unroll
        for (int nb = 0; nb < 8; nb++) {
            o[nb][0] *= corr0; o[nb][1] *= corr0;
            o[nb][2] *= corr1; o[nb][3] *= corr1;
        }

        // ---- O += P V (3-pass split; P from C-frag -> A-frag identity) ----
#pragma unroll
        for (int kc = 0; kc < 4; kc++) {
            unsigned ah[4], al[4];
            {
                float* p0 = s[2 * kc];
                float* p1 = s[2 * kc + 1];
                ah[0] = pack2bf(p0[0], p0[1]);
                ah[1] = pack2bf(p0[2], p0[3]);
                ah[2] = pack2bf(p1[0], p1[1]);
                ah[3] = pack2bf(p1[2], p1[3]);
                al[0] = pack2bf(p0[0] - bflo(ah[0]), p0[1] - bfhi(ah[0]));
                al[1] = pack2bf(p0[2] - bflo(ah[1]), p0[3] - bfhi(ah[1]));
                al[2] = pack2bf(p1[0] - bflo(ah[2]), p1[1] - bfhi(ah[2]));
                al[3] = pack2bf(p1[2] - bflo(ah[3]), p1[3] - bfhi(ah[3]));
            }
#pragma unroll
            for (int nb = 0; nb < 8; nb++) {
                unsigned Bh[2], Bl[2];
                uint32_t off = (uint32_t)(((kc * 16 + (lane & 15)) * GP2 + nb * 8) * 2);
                ldm_x2t(Bh, vh_u + off);
                ldm_x2t(Bl, vl_u + off);
                mma_bf16(o[nb], ah, Bh);
                mma_bf16(o[nb], ah, Bl);
                mma_bf16(o[nb], al, Bh);
            }
        }
    }

    // ---- epilogue ----
    const float i0 = 1.f / l0, i1 = 1.f / l1;
    float* out0 = g_attn + (size_t)(b * TT + rg0) * CC + h * HD + cbase;
    float* out1 = g_attn + (size_t)(b * TT + rg1) * CC + h * HD + cbase;
#pragma unroll
    for (int nb = 0; nb < 8; nb++) {
        *(float2*)(out0 + nb * 8) = make_float2(o[nb][0] * i0, o[nb][1] * i0);
        *(float2*)(out1 + nb * 8) = make_float2(o[nb][2] * i1, o[nb][3] * i1);
    }
}

// ---------------------------------------------------------------------------
extern "C" void kernel_launch(void* const* d_in, const int* in_sizes, int n_in,
                              void* d_out, int out_size)
{
    const float* x     = (const float*)d_in[0];   // (4096,1024)
    const float* w_qkv = (const float*)d_in[1];   // (3072,1024)
    const float* w_out = (const float*)d_in[2];   // (1024,1024)
    float* out = (float*)d_out;                   // (4096,1024)

    float* qkv;  cudaGetSymbolAddress((void**)&qkv,  g_qkv);
    float* attn; cudaGetSymbolAddress((void**)&attn, g_attn);

    const int M = BB * TT;

    static int attr_set = 0;
    if (!attr_set) {
        cudaFuncSetAttribute(gemm_bf16x3,
                             cudaFuncAttributeMaxDynamicSharedMemorySize,
                             GEMM_SMEM_BYTES);
        attr_set = 1;
    }

    gemm_bf16x3<<<dim3(C3 / 128, M / 128), 256, GEMM_SMEM_BYTES>>>(x, w_qkv, qkv, M, C3, CC);

    const int rope_total = BB * TT * HH * (HD / 2);
    rope_kernel<<<(rope_total + 255) / 256, 256>>>();

    attn_mma<<<dim3(TT / 64, BB * HH), 128>>>();

    gemm_bf16x3<<<dim3(CC / 128, M / 128), 256, GEMM_SMEM_BYTES>>>(attn, w_out, out, M, CC, CC);
}

// round 6
// speedup vs baseline: 3.1575x; 1.0882x over previous
#include <cuda_runtime.h>
#include <cuda_bf16.h>
#include <math.h>
#include <stdint.h>

#define BB 2
#define TT 2048
#define CC 1024
#define HH 16
#define HD 64
#define C3 3072

__device__ float g_qkv[(size_t)BB * TT * C3];   // 4096 x 3072
__device__ float g_attn[(size_t)BB * TT * CC];  // 4096 x 1024

// ---------------------------------------------------------------------------
// mma / ldmatrix helpers
// ---------------------------------------------------------------------------
__device__ __forceinline__ void mma_bf16(float* c, const unsigned* a, const unsigned* b) {
    asm("mma.sync.aligned.m16n8k16.row.col.f32.bf16.bf16.f32 "
        "{%0,%1,%2,%3},{%4,%5,%6,%7},{%8,%9},{%0,%1,%2,%3};"
        : "+f"(c[0]), "+f"(c[1]), "+f"(c[2]), "+f"(c[3])
        : "r"(a[0]), "r"(a[1]), "r"(a[2]), "r"(a[3]), "r"(b[0]), "r"(b[1]));
}
__device__ __forceinline__ void ldm_x4(unsigned* r, uint32_t addr) {
    asm volatile("ldmatrix.sync.aligned.m8n8.x4.shared.b16 {%0,%1,%2,%3}, [%4];"
                 : "=r"(r[0]), "=r"(r[1]), "=r"(r[2]), "=r"(r[3]) : "r"(addr));
}
__device__ __forceinline__ void ldm_x4t(unsigned* r, uint32_t addr) {
    asm volatile("ldmatrix.sync.aligned.m8n8.x4.trans.shared.b16 {%0,%1,%2,%3}, [%4];"
                 : "=r"(r[0]), "=r"(r[1]), "=r"(r[2]), "=r"(r[3]) : "r"(addr));
}

__device__ __forceinline__ unsigned pack2bf(float lo, float hi) {
    unsigned r;
    asm("cvt.rn.bf16x2.f32 %0, %1, %2;" : "=r"(r) : "f"(hi), "f"(lo));
    return r;
}
__device__ __forceinline__ float bflo(unsigned u) { return __uint_as_float(u << 16); }
__device__ __forceinline__ float bfhi(unsigned u) { return __uint_as_float(u & 0xffff0000u); }

// fast exp on fma/alu pipes (no MUFU)
__device__ __forceinline__ float fexp(float x) {
    float y = x * 1.4426950408889634f;
    y = fmaxf(y, -126.0f);
    int ni = __float2int_rd(y);
    float f = y - (float)ni;
    float p = 0.0018775767f;
    p = fmaf(p, f, 0.0089893397f);
    p = fmaf(p, f, 0.0558282185f);
    p = fmaf(p, f, 0.2400789568f);
    p = fmaf(p, f, 0.6931531203f);
    p = fmaf(p, f, 0.9999999702f);
    return __uint_as_float(__float_as_uint(p) + ((unsigned)ni << 23));
}

__device__ __forceinline__ void split4(float4 v, uint2& hp, uint2& lp) {
    unsigned h01 = pack2bf(v.x, v.y);
    unsigned h23 = pack2bf(v.z, v.w);
    float r0 = v.x - bflo(h01);
    float r1 = v.y - bfhi(h01);
    float r2 = v.z - bflo(h23);
    float r3 = v.w - bfhi(h23);
    hp = make_uint2(h01, h23);
    lp = make_uint2(pack2bf(r0, r1), pack2bf(r2, r3));
}

// ---------------------------------------------------------------------------
// Tensor-core GEMM (NT), bf16 3-term split.
// CTA 256x128, BK=16, 512 threads (16 warps, 4x4), warp tile 64x32.
// ---------------------------------------------------------------------------
#define GP 24
#define A_H (256 * GP)                  // 6144 halves
#define B_H (128 * GP)                  // 3072 halves
#define STAGE_H (2 * A_H + 2 * B_H)     // 18432 halves
#define GEMM_SMEM_BYTES (2 * STAGE_H * 2)   // 73728 B

__device__ __forceinline__ void cvt_store(unsigned short* hi_t, unsigned short* lo_t,
                                          int row, int col, float4 v) {
    uint2 hp, lp;
    split4(v, hp, lp);
    *(uint2*)&hi_t[row * GP + col] = hp;
    *(uint2*)&lo_t[row * GP + col] = lp;
}

__global__ __launch_bounds__(512, 1) void gemm_bf16x3(
    const float* __restrict__ A, const float* __restrict__ W,
    float* __restrict__ Cout, int M, int N, int K)
{
    extern __shared__ unsigned short sh[];

    const int tid = threadIdx.x;
    const int wid = tid >> 5;
    const int lane = tid & 31;
    const int warp_m = wid >> 2;        // 0..3 -> 64-row slices of 256
    const int warp_n = wid & 3;         // 0..3 -> 32-col slices of 128

    const float* Ap = A + (size_t)blockIdx.y * 256 * K;
    const float* Wp = W + (size_t)blockIdx.x * 128 * K;

    // A: 1024 float4 slots (256 rows x 4), thread covers tid, tid+512
    const int ar0 = tid >> 2,          ac0 = (tid & 3) * 4;
    const int ar1 = (tid + 512) >> 2,  ac1 = ((tid + 512) & 3) * 4;
    // B: 512 slots (128 rows x 4)
    const int br = tid >> 2,           bc = (tid & 3) * 4;

    const uint32_t smem_u32 = (uint32_t)__cvta_generic_to_shared(sh);

    const int a_lrow = (lane & 7) + ((lane >> 3) & 1) * 8;
    const int a_lcol = ((lane >> 4) & 1) * 8;

    float acc[4][4][4];
#pragma unroll
    for (int i = 0; i < 4; i++)
#pragma unroll
        for (int j = 0; j < 4; j++)
#pragma unroll
            for (int q = 0; q < 4; q++) acc[i][j][q] = 0.f;

    const int nstage = K / 16;

    float4 va0 = *(const float4*)(Ap + (size_t)ar0 * K + ac0);
    float4 va1 = *(const float4*)(Ap + (size_t)ar1 * K + ac1);
    float4 vb0 = *(const float4*)(Wp + (size_t)br * K + bc);
    cvt_store(sh,               sh + A_H,            ar0, ac0, va0);
    cvt_store(sh,               sh + A_H,            ar1, ac1, va1);
    cvt_store(sh + 2 * A_H,     sh + 2 * A_H + B_H,  br,  bc,  vb0);
    __syncthreads();

    for (int s = 0; s < nstage; s++) {
        if (s + 1 < nstage) {
            const int k0 = (s + 1) * 16;
            va0 = *(const float4*)(Ap + (size_t)ar0 * K + k0 + ac0);
            va1 = *(const float4*)(Ap + (size_t)ar1 * K + k0 + ac1);
            vb0 = *(const float4*)(Wp + (size_t)br * K + k0 + bc);
        }
        {
            const uint32_t base = smem_u32 + (unsigned)(s & 1) * (STAGE_H * 2);
            const uint32_t baseAhi = base;
            const uint32_t baseAlo = base + A_H * 2;
            const uint32_t baseBhi = base + 2 * A_H * 2;
            const uint32_t baseBlo = base + (2 * A_H + B_H) * 2;

            // hold all B fragments (x4: two n-blocks per load)
            unsigned Bh[2][4], Bl[2][4];
#pragma unroll
            for (int anp = 0; anp < 2; anp++) {
                const uint32_t off = (uint32_t)(((warp_n * 32 + anp * 16 +
                                                  ((lane >> 4) & 1) * 8 + (lane & 7)) * GP +
                                                 ((lane >> 3) & 1) * 8) * 2);
                ldm_x4(Bh[anp], baseBhi + off);
                ldm_x4(Bl[anp], baseBlo + off);
            }
#pragma unroll
            for (int am = 0; am < 4; am++) {
                unsigned Ah[4], Al[4];
                const uint32_t off =
                    (uint32_t)(((warp_m * 64 + am * 16 + a_lrow) * GP + a_lcol) * 2);
                ldm_x4(Ah, baseAhi + off);
                ldm_x4(Al, baseAlo + off);
#pragma unroll
                for (int anp = 0; anp < 2; anp++) {
                    mma_bf16(acc[am][2 * anp],     Ah, &Bh[anp][0]);
                    mma_bf16(acc[am][2 * anp + 1], Ah, &Bh[anp][2]);
                    mma_bf16(acc[am][2 * anp],     Ah, &Bl[anp][0]);
                    mma_bf16(acc[am][2 * anp + 1], Ah, &Bl[anp][2]);
                    mma_bf16(acc[am][2 * anp],     Al, &Bh[anp][0]);
                    mma_bf16(acc[am][2 * anp + 1], Al, &Bh[anp][2]);
                }
            }
        }
        if (s + 1 < nstage) {
            unsigned short* st = sh + (unsigned)((s + 1) & 1) * STAGE_H;
            cvt_store(st,           st + A_H,           ar0, ac0, va0);
            cvt_store(st,           st + A_H,           ar1, ac1, va1);
            cvt_store(st + 2 * A_H, st + 2 * A_H + B_H, br,  bc,  vb0);
            __syncthreads();
        }
    }

    const int mbase = blockIdx.y * 256 + warp_m * 64 + (lane >> 2);
    const int nbase = blockIdx.x * 128 + warp_n * 32 + (lane & 3) * 2;
#pragma unroll
    for (int am = 0; am < 4; am++) {
#pragma unroll
        for (int an = 0; an < 4; an++) {
            const int r = mbase + am * 16;
            const int c = nbase + an * 8;
            *(float2*)&Cout[(size_t)r * N + c]       = make_float2(acc[am][an][0], acc[am][an][1]);
            *(float2*)&Cout[(size_t)(r + 8) * N + c] = make_float2(acc[am][an][2], acc[am][an][3]);
        }
    }
}

// ---------------------------------------------------------------------------
// RoPE: in-place on q and k slices of g_qkv.
// ---------------------------------------------------------------------------
__global__ void rope_kernel()
{
    int i = blockIdx.x * blockDim.x + threadIdx.x;
    const int total = BB * TT * HH * (HD / 2);
    if (i >= total) return;

    int n = i >> 9;
    int r = i & 511;
    int h = r >> 5;
    int j = r & 31;
    int t = n & (TT - 1);

    float inv_freq = (float)exp(-(double)j * 0.28782313662425575);
    float f = (float)t * inv_freq;
    float c = cosf(f);
    float s = sinf(f);

    float* p = g_qkv + (size_t)n * C3 + h * HD + 2 * j;
    float qr = p[0], qi = p[1];
    p[0] = qr * c - qi * s;
    p[1] = qr * s + qi * c;

    float* pk = p + CC;
    float kr = pk[0], ki = pk[1];
    pk[0] = kr * c - ki * s;
    pk[1] = kr * s + ki * c;
}

// ---------------------------------------------------------------------------
// Tensor-core causal flash attention.
// CTA: 128 q-rows, 8 warps (16 rows/warp), 64-key tiles, dynamic smem.
// ---------------------------------------------------------------------------
#define GP2 72
// halves offsets within dynamic smem
#define KHI_O 0
#define KLO_O 4608
#define VHI_O 9216
#define VLO_O 13824
#define QHI_O 18432
#define QLO_O 27648
#define ATTN_SMEM_HALVES 36864
#define ATTN_SMEM_BYTES (ATTN_SMEM_HALVES * 2)   // 73728 B

__global__ __launch_bounds__(256) void attn_mma()
{
    extern __shared__ unsigned short ash[];

    const int bh = blockIdx.y;
    const int b = bh >> 4;
    const int h = bh & 15;
    const int qtile = 15 - blockIdx.x;     // heavy tiles first
    const int q0 = qtile * 128;
    const int tid = threadIdx.x;
    const int wid = tid >> 5;
    const int lane = tid & 31;
    const float scale = 0.125f;

    const float* base = g_qkv + (size_t)b * TT * C3;

    const uint32_t sm_u = (uint32_t)__cvta_generic_to_shared(ash);
    const uint32_t kh_u = sm_u + KHI_O * 2;
    const uint32_t kl_u = sm_u + KLO_O * 2;
    const uint32_t vh_u = sm_u + VHI_O * 2;
    const uint32_t vl_u = sm_u + VLO_O * 2;
    const uint32_t qh_u = sm_u + QHI_O * 2;
    const uint32_t ql_u = sm_u + QLO_O * 2;

    const int a_lrow = (lane & 7) + ((lane >> 3) & 1) * 8;
    const int a_lcol = ((lane >> 4) & 1) * 8;

    // ---- stage Q (128 x 64) ----
#pragma unroll
    for (int it = 0; it < 8; it++) {
        int idx = tid + it * 256;               // 2048 float4 slots
        int r = idx >> 4, c4 = (idx & 15) * 4;
        float4 v = *(const float4*)(base + (size_t)(q0 + r) * C3 + h * HD + c4);
        uint2 hp, lp;
        split4(v, hp, lp);
        *(uint2*)&ash[QHI_O + r * GP2 + c4] = hp;
        *(uint2*)&ash[QLO_O + r * GP2 + c4] = lp;
    }
    __syncthreads();

    unsigned Qh[4][4], Ql[4][4];
#pragma unroll
    for (int kk = 0; kk < 4; kk++) {
        uint32_t off = (uint32_t)(((wid * 16 + a_lrow) * GP2 + kk * 16 + a_lcol) * 2);
        ldm_x4(Qh[kk], qh_u + off);
        ldm_x4(Ql[kk], ql_u + off);
    }

    float o[8][4];
#pragma unroll
    for (int nb = 0; nb < 8; nb++)
#pragma unroll
        for (int e = 0; e < 4; e++) o[nb][e] = 0.f;
    float m0 = -1e30f, m1 = -1e30f, l0 = 0.f, l1 = 0.f;

    const int rg0 = q0 + wid * 16 + (lane >> 2);
    const int rg1 = rg0 + 8;
    const int cbase = (lane & 3) * 2;

    const int nkt = 2 * qtile + 2;
    for (int kt = 0; kt < nkt; kt++) {
        const int k0 = kt * 64;
        __syncthreads();

        // ---- load K,V tile (64 x 64), split bf16 hi/lo ----
#pragma unroll
        for (int it = 0; it < 4; it++) {
            int idx = tid + it * 256;            // 1024 slots
            int r = idx >> 4, c4 = (idx & 15) * 4;
            const float* src = base + (size_t)(k0 + r) * C3 + CC + h * HD + c4;
            float4 kv = *(const float4*)src;
            float4 vv = *(const float4*)(src + CC);
            uint2 hp, lp;
            split4(kv, hp, lp);
            *(uint2*)&ash[KHI_O + r * GP2 + c4] = hp;
            *(uint2*)&ash[KLO_O + r * GP2 + c4] = lp;
            split4(vv, hp, lp);
            *(uint2*)&ash[VHI_O + r * GP2 + c4] = hp;
            *(uint2*)&ash[VLO_O + r * GP2 + c4] = lp;
        }
        __syncthreads();

        // ---- S = Q K^T (3-pass split, x4 B loads) ----
        float s[8][4];
#pragma unroll
        for (int nb = 0; nb < 8; nb++)
#pragma unroll
            for (int e = 0; e < 4; e++) s[nb][e] = 0.f;

#pragma unroll
        for (int kk = 0; kk < 4; kk++) {
#pragma unroll
            for (int nbp = 0; nbp < 4; nbp++) {
                unsigned Bh[4], Bl[4];
                uint32_t off = (uint32_t)(((nbp * 16 + ((lane >> 4) & 1) * 8 + (lane & 7)) * GP2 +
                                           kk * 16 + ((lane >> 3) & 1) * 8) * 2);
                ldm_x4(Bh, kh_u + off);
                ldm_x4(Bl, kl_u + off);
                mma_bf16(s[2 * nbp],     Qh[kk], &Bh[0]);
                mma_bf16(s[2 * nbp + 1], Qh[kk], &Bh[2]);
                mma_bf16(s[2 * nbp],     Qh[kk], &Bl[0]);
                mma_bf16(s[2 * nbp + 1], Qh[kk], &Bl[2]);
                mma_bf16(s[2 * nbp],     Ql[kk], &Bh[0]);
                mma_bf16(s[2 * nbp + 1], Ql[kk], &Bh[2]);
            }
        }

        // ---- scale + causal mask ----
        const bool diag = (kt >= 2 * qtile);
#pragma unroll
        for (int nb = 0; nb < 8; nb++) {
            int c0g = k0 + nb * 8 + cbase;
#pragma unroll
            for (int e = 0; e < 4; e++) {
                int col = c0g + (e & 1);
                int row = (e < 2) ? rg0 : rg1;
                float v = s[nb][e] * scale;
                if (diag && col > row) v = -1e30f;
                s[nb][e] = v;
            }
        }

        // ---- online softmax ----
        float mx0 = -1e30f, mx1 = -1e30f;
#pragma unroll
        for (int nb = 0; nb < 8; nb++) {
            mx0 = fmaxf(mx0, fmaxf(s[nb][0], s[nb][1]));
            mx1 = fmaxf(mx1, fmaxf(s[nb][2], s[nb][3]));
        }
        mx0 = fmaxf(mx0, __shfl_xor_sync(0xffffffffu, mx0, 1));
        mx0 = fmaxf(mx0, __shfl_xor_sync(0xffffffffu, mx0, 2));
        mx1 = fmaxf(mx1, __shfl_xor_sync(0xffffffffu, mx1, 1));
        mx1 = fmaxf(mx1, __shfl_xor_sync(0xffffffffu, mx1, 2));

        float nm0 = fmaxf(m0, mx0), nm1 = fmaxf(m1, mx1);
        float corr0 = fexp(m0 - nm0), corr1 = fexp(m1 - nm1);
        m0 = nm0; m1 = nm1;

        float ls0 = 0.f, ls1 = 0.f;
#pragma unroll
        for (int nb = 0; nb < 8; nb++) {
            s[nb][0] = fexp(s[nb][0] - nm0); ls0 += s[nb][0];
            s[nb][1] = fexp(s[nb][1] - nm0); ls0 += s[nb][1];
            s[nb][2] = fexp(s[nb][2] - nm1); ls1 += s[nb][2];
            s[nb][3] = fexp(s[nb][3] - nm1); ls1 += s[nb][3];
        }
        ls0 += __shfl_xor_sync(0xffffffffu, ls0, 1);
        ls0 += __shfl_xor_sync(0xffffffffu, ls0, 2);
        ls1 += __shfl_xor_sync(0xffffffffu, ls1, 1);
        ls1 += __shfl_xor_sync(0xffffffffu, ls1, 2);
        l0 = l0 * corr0 + ls0;
        l1 = l1 * corr1 + ls1;

#pragma unroll
        for (int nb = 0; nb < 8; nb++) {
            o[nb][0] *= corr0; o[nb][1] *= corr0;
            o[nb][2] *= corr1; o[nb][3] *= corr1;
        }

        // ---- O += P V (3-pass split, x4 trans B loads) ----
#pragma unroll
        for (int kc = 0; kc < 4; kc++) {
            unsigned ah[4], al[4];
            {
                float* p0 = s[2 * kc];
                float* p1 = s[2 * kc + 1];
                ah[0] = pack2bf(p0[0], p0[1]);
                ah[1] = pack2bf(p0[2], p0[3]);
                ah[2] = pack2bf(p1[0], p1[1]);
                ah[3] = pack2bf(p1[2], p1[3]);
                al[0] = pack2bf(p0[0] - bflo(ah[0]), p0[1] - bfhi(ah[0]));
                al[1] = pack2bf(p0[2] - bflo(ah[1]), p0[3] - bfhi(ah[1]));
                al[2] = pack2bf(p1[0] - bflo(ah[2]), p1[1] - bfhi(ah[2]));
                al[3] = pack2bf(p1[2] - bflo(ah[3]), p1[3] - bfhi(ah[3]));
            }
#pragma unroll
            for (int nbp = 0; nbp < 4; nbp++) {
                unsigned Bh[4], Bl[4];
                uint32_t off = (uint32_t)(((kc * 16 + (lane & 15)) * GP2 +
                                           (nbp * 2 + ((lane >> 4) & 1)) * 8) * 2);
                ldm_x4t(Bh, vh_u + off);
                ldm_x4t(Bl, vl_u + off);
                mma_bf16(o[2 * nbp],     ah, &Bh[0]);
                mma_bf16(o[2 * nbp + 1], ah, &Bh[2]);
                mma_bf16(o[2 * nbp],     ah, &Bl[0]);
                mma_bf16(o[2 * nbp + 1], ah, &Bl[2]);
                mma_bf16(o[2 * nbp],     al, &Bh[0]);
                mma_bf16(o[2 * nbp + 1], al, &Bh[2]);
            }
        }
    }

    // ---- epilogue ----
    const float i0 = 1.f / l0, i1 = 1.f / l1;
    float* out0 = g_attn + (size_t)(b * TT + rg0) * CC + h * HD + cbase;
    float* out1 = g_attn + (size_t)(b * TT + rg1) * CC + h * HD + cbase;
#pragma unroll
    for (int nb = 0; nb < 8; nb++) {
        *(float2*)(out0 + nb * 8) = make_float2(o[nb][0] * i0, o[nb][1] * i0);
        *(float2*)(out1 + nb * 8) = make_float2(o[nb][2] * i1, o[nb][3] * i1);
    }
}

// ---------------------------------------------------------------------------
extern "C" void kernel_launch(void* const* d_in, const int* in_sizes, int n_in,
                              void* d_out, int out_size)
{
    const float* x     = (const float*)d_in[0];   // (4096,1024)
    const float* w_qkv = (const float*)d_in[1];   // (3072,1024)
    const float* w_out = (const float*)d_in[2];   // (1024,1024)
    float* out = (float*)d_out;                   // (4096,1024)

    float* qkv;  cudaGetSymbolAddress((void**)&qkv,  g_qkv);
    float* attn; cudaGetSymbolAddress((void**)&attn, g_attn);

    const int M = BB * TT;

    static int attr_set = 0;
    if (!attr_set) {
        cudaFuncSetAttribute(gemm_bf16x3,
                             cudaFuncAttributeMaxDynamicSharedMemorySize,
                             GEMM_SMEM_BYTES);
        cudaFuncSetAttribute(attn_mma,
                             cudaFuncAttributeMaxDynamicSharedMemorySize,
                             ATTN_SMEM_BYTES);
        attr_set = 1;
    }

    gemm_bf16x3<<<dim3(C3 / 128, M / 256), 512, GEMM_SMEM_BYTES>>>(x, w_qkv, qkv, M, C3, CC);

    const int rope_total = BB * TT * HH * (HD / 2);
    rope_kernel<<<(rope_total + 255) / 256, 256>>>();

    attn_mma<<<dim3(TT / 128, BB * HH), 256, ATTN_SMEM_BYTES>>>();

    gemm_bf16x3<<<dim3(CC / 128, M / 256), 512, GEMM_SMEM_BYTES>>>(attn, w_out, out, M, CC, CC);
}